// round 4
// baseline (speedup 1.0000x reference)
#include <cuda_runtime.h>
#include <cstdint>

// Problem: B=2, N=2048, C=1024, H=16, D=64
// g_q/g_k layout: [bh=32][n=2048][128], d 0..63 real, 64..127 imag.
// g_v layout:     [bh=32][d=128][n=2048]   (d-major, written by proj)
// g_z layout:     [b*2048+n][2048] = [out_r(1024) | out_i(1024)]

#define PROJ_SMEM (2 * 2 * 128 * 36 * 4)                              // 73728 B
#define ATT_SMEM  ((128 * 132 + 64 * 132 + 128 * 68 + 128 * 68) * 4)  // 171008 B

__device__ float g_q[32 * 2048 * 128];
__device__ float g_k[32 * 2048 * 128];
__device__ float g_v[32 * 128 * 2048];
__device__ float g_z[4096 * 2048];

// ---------------------------------------------------------------------------
// helpers
// ---------------------------------------------------------------------------
__device__ __forceinline__ float tf32f(float x) {
    uint32_t r;
    asm("cvt.rna.tf32.f32 %0, %1;" : "=r"(r) : "f"(x));
    return __int_as_float(r);
}
__device__ __forceinline__ uint32_t u32(float x) { return __float_as_uint(x); }

__device__ __forceinline__ void mma8(float* d,
                                     uint32_t a0, uint32_t a1, uint32_t a2, uint32_t a3,
                                     uint32_t b0, uint32_t b1) {
    asm volatile(
        "mma.sync.aligned.m16n8k8.row.col.f32.tf32.tf32.f32 "
        "{%0,%1,%2,%3}, {%4,%5,%6,%7}, {%8,%9}, {%0,%1,%2,%3};"
        : "+f"(d[0]), "+f"(d[1]), "+f"(d[2]), "+f"(d[3])
        : "r"(a0), "r"(a1), "r"(a2), "r"(a3), "r"(b0), "r"(b1));
}

// sqrt on the FMA pipe: bithack rsqrt + 2 Newton iterations
__device__ __forceinline__ float sqrt_nr(float h) {
    h = fmaxf(h, 1e-24f);
    float x = __int_as_float(0x5f3759df - (__float_as_int(h) >> 1));
    float hh = 0.5f * h;
    x = x * fmaf(-hh * x, x, 1.5f);
    x = x * fmaf(-hh * x, x, 1.5f);
    return h * x;
}

// exp2 on the FMA/ALU pipes. Valid for |z| < 120.
__device__ __forceinline__ float exp2p(float z) {
    float r = z + 12582912.0f;
    int n = __float_as_int(r) - 0x4B400000;
    float f = z - (r - 12582912.0f);
    float p = 1.3333558e-3f;
    p = fmaf(p, f, 9.6181291e-3f);
    p = fmaf(p, f, 5.5504109e-2f);
    p = fmaf(p, f, 2.4022651e-1f);
    p = fmaf(p, f, 6.9314718e-1f);
    p = fmaf(p, f, 1.0f);
    return __int_as_float(__float_as_int(p) + (n << 23));
}

// ---------------------------------------------------------------------------
// Input projections: blockIdx.z = 0/1/2 -> Q/K/V.
// BM=128, BN=128, BK=32, double-buffered smem, tf32 mma.
// smem k-columns permuted: col c (0..31) stored at p = (c&3)*8 + (c>>2),
// so a thread's 8 fragment values (cols tg+4j) are contiguous -> LDS.128.
// V output written d-major: g_v[bh][d][n].
// ---------------------------------------------------------------------------
__global__ void __launch_bounds__(256) proj_mma_kernel(
    const float* __restrict__ X,
    const float* __restrict__ qrw, const float* __restrict__ qrb,
    const float* __restrict__ qiw, const float* __restrict__ qib,
    const float* __restrict__ krw, const float* __restrict__ krb,
    const float* __restrict__ kiw, const float* __restrict__ kib,
    const float* __restrict__ vrw, const float* __restrict__ vrb,
    const float* __restrict__ viw, const float* __restrict__ vib)
{
    extern __shared__ float sm[];
    float* As = sm;                 // [2][128][36] permuted
    float* Bs = sm + 2 * 128 * 36;  // [2][128][36] permuted

    const int t = threadIdx.x;
    const int w = t >> 5, lane = t & 31, g = lane >> 2, tg = lane & 3;
    const int wm = w >> 2, wn = w & 3;
    const int z = blockIdx.z;
    const int bx = blockIdx.x;
    const int m0 = blockIdx.y * 128;
    const bool imag = bx >= 8;
    const float* W;
    const float* bias;
    float* Out;
    if (z == 0)      { W = imag ? qiw : qrw; bias = imag ? qib : qrb; Out = g_q; }
    else if (z == 1) { W = imag ? kiw : krw; bias = imag ? kib : krb; Out = g_k; }
    else             { W = imag ? viw : vrw; bias = imag ? vib : vrb; Out = g_v; }
    const int o0 = (bx & 7) * 128;

    int lrow[4], lc4[4];
    #pragma unroll
    for (int i = 0; i < 4; i++) { int idx = i * 256 + t; lrow[i] = idx >> 3; lc4[i] = (idx & 7) * 4; }

    const float* Ag = X + (size_t)m0 * 1024;
    const float* Bg = W + (size_t)o0 * 1024;

    float acc[4][4][4];
    #pragma unroll
    for (int a = 0; a < 4; a++)
        #pragma unroll
        for (int b = 0; b < 4; b++)
            #pragma unroll
            for (int c = 0; c < 4; c++) acc[a][b][c] = 0.f;

    float4 pa[4], pb[4];
    #pragma unroll
    for (int i = 0; i < 4; i++) {
        pa[i] = *(const float4*)(Ag + lrow[i] * 1024 + lc4[i]);
        pb[i] = *(const float4*)(Bg + lrow[i] * 1024 + lc4[i]);
    }
    #pragma unroll
    for (int i = 0; i < 4; i++) {
        int q = lc4[i] >> 2;
        float* d = As + lrow[i] * 36 + q;
        d[0] = tf32f(pa[i].x); d[8] = tf32f(pa[i].y); d[16] = tf32f(pa[i].z); d[24] = tf32f(pa[i].w);
        float* e = Bs + lrow[i] * 36 + q;
        e[0] = tf32f(pb[i].x); e[8] = tf32f(pb[i].y); e[16] = tf32f(pb[i].z); e[24] = tf32f(pb[i].w);
    }
    __syncthreads();

    for (int ktile = 0; ktile < 32; ktile++) {
        const int cur = ktile & 1;
        if (ktile + 1 < 32) {
            int k0 = (ktile + 1) * 32;
            #pragma unroll
            for (int i = 0; i < 4; i++) {
                pa[i] = *(const float4*)(Ag + lrow[i] * 1024 + k0 + lc4[i]);
                pb[i] = *(const float4*)(Bg + lrow[i] * 1024 + k0 + lc4[i]);
            }
        }
        const float* Ab = As + cur * 128 * 36;
        const float* Bb = Bs + cur * 128 * 36;
        #pragma unroll
        for (int ks2 = 0; ks2 < 2; ks2++) {
            const int off = tg * 8 + 4 * ks2;
            float4 a0[4], a8[4];
            #pragma unroll
            for (int mt = 0; mt < 4; mt++) {
                const float* ap = Ab + (64 * wm + 16 * mt + g) * 36 + off;
                a0[mt] = *(const float4*)ap;
                a8[mt] = *(const float4*)(ap + 8 * 36);
            }
            #pragma unroll
            for (int nt = 0; nt < 4; nt++) {
                float4 bv = *(const float4*)(Bb + (32 * wn + 8 * nt + g) * 36 + off);
                #pragma unroll
                for (int mt = 0; mt < 4; mt++) {
                    mma8(acc[mt][nt], u32(a0[mt].x), u32(a8[mt].x), u32(a0[mt].y), u32(a8[mt].y),
                         u32(bv.x), u32(bv.y));
                    mma8(acc[mt][nt], u32(a0[mt].z), u32(a8[mt].z), u32(a0[mt].w), u32(a8[mt].w),
                         u32(bv.z), u32(bv.w));
                }
            }
        }
        if (ktile + 1 < 32) {
            float* dA = As + (1 - cur) * 128 * 36;
            float* dB = Bs + (1 - cur) * 128 * 36;
            #pragma unroll
            for (int i = 0; i < 4; i++) {
                int q = lc4[i] >> 2;
                float* d = dA + lrow[i] * 36 + q;
                d[0] = tf32f(pa[i].x); d[8] = tf32f(pa[i].y); d[16] = tf32f(pa[i].z); d[24] = tf32f(pa[i].w);
                float* e = dB + lrow[i] * 36 + q;
                e[0] = tf32f(pb[i].x); e[8] = tf32f(pb[i].y); e[16] = tf32f(pb[i].z); e[24] = tf32f(pb[i].w);
            }
        }
        __syncthreads();
    }

    // epilogue
    const int part = imag ? 1 : 0;
    const int ob = o0 + 32 * wn;
    const int hh = ob >> 6;
    if (z == 2) {
        // V: write d-major [bh][d][n]
        #pragma unroll
        for (int mt = 0; mt < 4; mt++) {
            int m = m0 + 64 * wm + 16 * mt + g;
            #pragma unroll
            for (int r = 0; r < 2; r++) {
                int mm = m + 8 * r;
                int b_ = mm >> 11, nn = mm & 2047;
                #pragma unroll
                for (int nt = 0; nt < 4; nt++) {
                    int o = ob + 8 * nt + 2 * tg;
                    float2 bv = *(const float2*)(bias + o);
                    size_t vrow = (size_t)(b_ * 16 + hh) * 128 + part * 64 + (o & 63);
                    g_v[vrow * 2048 + nn]       = acc[mt][nt][2 * r + 0] + bv.x;
                    g_v[(vrow + 1) * 2048 + nn] = acc[mt][nt][2 * r + 1] + bv.y;
                }
            }
        }
    } else {
        #pragma unroll
        for (int mt = 0; mt < 4; mt++) {
            int m = m0 + 64 * wm + 16 * mt + g;
            #pragma unroll
            for (int r = 0; r < 2; r++) {
                int mm = m + 8 * r;
                int b_ = mm >> 11, nn = mm & 2047;
                float* dst = Out + ((size_t)(b_ * 16 + hh) * 2048 + nn) * 128 + part * 64;
                #pragma unroll
                for (int nt = 0; nt < 4; nt++) {
                    int o = ob + 8 * nt + 2 * tg;
                    float2 bv = *(const float2*)(bias + o);
                    *(float2*)(dst + (o & 63)) =
                        make_float2(acc[mt][nt][2 * r + 0] + bv.x, acc[mt][nt][2 * r + 1] + bv.y);
                }
            }
        }
    }
}

// ---------------------------------------------------------------------------
// Fused complex-magnitude attention, tf32 mma + FMA-pipe softmax.
// Block = 128 queries x one bh; 8 warps, 16 query rows each; 64-key tiles.
// Q/K smem: [row][132], d-cols permuted per 64-half: p = (c&3)*16 + (c>>2).
// V smem:   [d=128][68], keys permuted (loaded from d-major g_v).
// P smem:   [query=128][68], keys permuted.
// Fixed-shift softmax: p = exp2(0.18034*s - 11.5416) == exp(0.125*|s| - 8).
// ---------------------------------------------------------------------------
__global__ void __launch_bounds__(256) attn_mma_kernel()
{
    extern __shared__ float sm[];
    float* Qs = sm;                  // [128][132]
    float* Ks = Qs + 128 * 132;      // [64][132]
    float* Vs = Ks + 64 * 132;       // [128][68]  (d rows, permuted keys)
    float* Ps = Vs + 128 * 68;       // [128][68]  (query rows, permuted keys)

    const int t = threadIdx.x;
    const int w = t >> 5, lane = t & 31, g = lane >> 2, tg = lane & 3;
    const int bh = blockIdx.y;
    const int q0 = blockIdx.x * 128;

    const float* Qg = g_q + ((size_t)bh * 2048 + q0) * 128;
    const float* Kg = g_k + (size_t)bh * 2048 * 128;
    const float* Vg = g_v + (size_t)bh * 128 * 2048;

    // load Q tile with per-64 d-permutation
    #pragma unroll
    for (int i = 0; i < 16; i++) {
        int idx = i * 256 + t;
        int row = idx >> 5, c4 = (idx & 31) * 4;
        float4 v = *(const float4*)(Qg + row * 128 + c4);
        int grp = c4 >> 6, q = (c4 & 63) >> 2;
        float* d = Qs + row * 132 + grp * 64 + q;
        d[0] = tf32f(v.x); d[16] = tf32f(v.y); d[32] = tf32f(v.z); d[48] = tf32f(v.w);
    }

    float O[16][4];
    #pragma unroll
    for (int i = 0; i < 16; i++) { O[i][0] = 0.f; O[i][1] = 0.f; O[i][2] = 0.f; O[i][3] = 0.f; }
    float l0 = 0.f, l1 = 0.f;

    const int qrow = 16 * w;
    const float K1 = 0.18033688f;   // 0.125 * log2(e)
    const float K2 = -11.541560f;   // -8 * log2(e)

    for (int kt = 0; kt < 32; kt++) {
        __syncthreads();   // previous tile's readers of Ks/Vs done (Qs ready on 1st)
        const float* Kt = Kg + (size_t)kt * 64 * 128;
        const float* Vt = Vg + kt * 64;
        #pragma unroll
        for (int i = 0; i < 8; i++) {
            int idx = i * 256 + t;
            // K: [key=64][128 d permuted]
            int row = idx >> 5, c4 = (idx & 31) * 4;
            float4 kv = *(const float4*)(Kt + row * 128 + c4);
            int grp = c4 >> 6, q = (c4 & 63) >> 2;
            float* dk = Ks + row * 132 + grp * 64 + q;
            dk[0] = tf32f(kv.x); dk[16] = tf32f(kv.y); dk[32] = tf32f(kv.z); dk[48] = tf32f(kv.w);
            // V: [d=128][64 keys permuted]
            int dr = idx >> 4, k4 = (idx & 15) * 4;
            float4 vv = *(const float4*)(Vt + (size_t)dr * 2048 + k4);
            float* dv = Vs + dr * 68 + (k4 >> 2);
            dv[0] = tf32f(vv.x); dv[16] = tf32f(vv.y); dv[32] = tf32f(vv.z); dv[48] = tf32f(vv.w);
        }
        __syncthreads();

        float Sr[8][4], Si[8][4];
        #pragma unroll
        for (int i = 0; i < 8; i++) {
            Sr[i][0] = 0.f; Sr[i][1] = 0.f; Sr[i][2] = 0.f; Sr[i][3] = 0.f;
            Si[i][0] = 0.f; Si[i][1] = 0.f; Si[i][2] = 0.f; Si[i][3] = 0.f;
        }

        #pragma unroll
        for (int ks2 = 0; ks2 < 4; ks2++) {
            const int off = tg * 16 + 4 * ks2;
            const float* q0p = Qs + (qrow + g) * 132 + off;
            const float* q8p = Qs + (qrow + g + 8) * 132 + off;
            float4 q0r = *(const float4*)q0p;
            float4 q8r = *(const float4*)q8p;
            float4 q0i = *(const float4*)(q0p + 64);
            float4 q8i = *(const float4*)(q8p + 64);
            uint32_t n0x = u32(q0r.x) ^ 0x80000000u, n8x = u32(q8r.x) ^ 0x80000000u;
            uint32_t n0y = u32(q0r.y) ^ 0x80000000u, n8y = u32(q8r.y) ^ 0x80000000u;
            uint32_t n0z = u32(q0r.z) ^ 0x80000000u, n8z = u32(q8r.z) ^ 0x80000000u;
            uint32_t n0w = u32(q0r.w) ^ 0x80000000u, n8w = u32(q8r.w) ^ 0x80000000u;
            #pragma unroll
            for (int nt = 0; nt < 8; nt++) {
                const float* kp = Ks + (8 * nt + g) * 132 + off;
                float4 kr4 = *(const float4*)kp;
                float4 ki4 = *(const float4*)(kp + 64);
                // ks a
                mma8(Sr[nt], u32(q0r.x), u32(q8r.x), u32(q0r.y), u32(q8r.y), u32(kr4.x), u32(kr4.y));
                mma8(Sr[nt], u32(q0i.x), u32(q8i.x), u32(q0i.y), u32(q8i.y), u32(ki4.x), u32(ki4.y));
                mma8(Si[nt], u32(q0i.x), u32(q8i.x), u32(q0i.y), u32(q8i.y), u32(kr4.x), u32(kr4.y));
                mma8(Si[nt], n0x, n8x, n0y, n8y, u32(ki4.x), u32(ki4.y));
                // ks b
                mma8(Sr[nt], u32(q0r.z), u32(q8r.z), u32(q0r.w), u32(q8r.w), u32(kr4.z), u32(kr4.w));
                mma8(Sr[nt], u32(q0i.z), u32(q8i.z), u32(q0i.w), u32(q8i.w), u32(ki4.z), u32(ki4.w));
                mma8(Si[nt], u32(q0i.z), u32(q8i.z), u32(q0i.w), u32(q8i.w), u32(kr4.z), u32(kr4.w));
                mma8(Si[nt], n0z, n8z, n0w, n8w, u32(ki4.z), u32(ki4.w));
            }
        }

        // magnitude + exp on FMA/ALU pipes; accumulate l; store P (key-permuted)
        float* pr0 = Ps + (qrow + g) * 68;
        float* pr8 = Ps + (qrow + g + 8) * 68;
        const int pb = (tg & 1) * 32 + (tg >> 1);
        #pragma unroll
        for (int nt = 0; nt < 8; nt++) {
            float h0 = fmaf(Si[nt][0], Si[nt][0], Sr[nt][0] * Sr[nt][0]);
            float h1 = fmaf(Si[nt][1], Si[nt][1], Sr[nt][1] * Sr[nt][1]);
            float h2 = fmaf(Si[nt][2], Si[nt][2], Sr[nt][2] * Sr[nt][2]);
            float h3 = fmaf(Si[nt][3], Si[nt][3], Sr[nt][3] * Sr[nt][3]);
            float p0 = exp2p(fmaf(sqrt_nr(h0), K1, K2));
            float p1 = exp2p(fmaf(sqrt_nr(h1), K1, K2));
            float p2 = exp2p(fmaf(sqrt_nr(h2), K1, K2));
            float p3 = exp2p(fmaf(sqrt_nr(h3), K1, K2));
            l0 += p0 + p1;
            l1 += p2 + p3;
            pr0[pb + 2 * nt]      = tf32f(p0);
            pr0[pb + 2 * nt + 16] = tf32f(p1);
            pr8[pb + 2 * nt]      = tf32f(p2);
            pr8[pb + 2 * nt + 16] = tf32f(p3);
        }
        __syncwarp();   // each warp reads only its own 16 P rows

        // O += P @ Vt  (n dim = d features, k dim = keys)
        #pragma unroll
        for (int ks2 = 0; ks2 < 4; ks2++) {
            const int off = tg * 16 + 4 * ks2;
            float4 p0 = *(const float4*)(Ps + (qrow + g) * 68 + off);
            float4 p8 = *(const float4*)(Ps + (qrow + g + 8) * 68 + off);
            #pragma unroll
            for (int nt = 0; nt < 16; nt++) {
                float4 vv = *(const float4*)(Vs + (8 * nt + g) * 68 + off);
                mma8(O[nt], u32(p0.x), u32(p8.x), u32(p0.y), u32(p8.y), u32(vv.x), u32(vv.y));
                mma8(O[nt], u32(p0.z), u32(p8.z), u32(p0.w), u32(p8.w), u32(vv.z), u32(vv.w));
            }
        }
    }

    // epilogue: divide by row sums, write merged-head layout into g_z
    l0 += __shfl_xor_sync(0xffffffffu, l0, 1);
    l0 += __shfl_xor_sync(0xffffffffu, l0, 2);
    l1 += __shfl_xor_sync(0xffffffffu, l1, 1);
    l1 += __shfl_xor_sync(0xffffffffu, l1, 2);
    const float inv0 = 1.f / l0, inv1 = 1.f / l1;

    const int b_ = bh >> 4, hh = bh & 15;
    const int q = q0 + qrow + g;
    float* dst0 = g_z + (size_t)(b_ * 2048 + q) * 2048;
    float* dst1 = g_z + (size_t)(b_ * 2048 + q + 8) * 2048;
    #pragma unroll
    for (int nt = 0; nt < 16; nt++) {
        int d0 = 8 * nt + 2 * tg;
        int col = (d0 >> 6) * 1024 + hh * 64 + (d0 & 63);
        *(float2*)(dst0 + col) = make_float2(O[nt][0] * inv0, O[nt][1] * inv0);
        *(float2*)(dst1 + col) = make_float2(O[nt][2] * inv1, O[nt][3] * inv1);
    }
}

// ---------------------------------------------------------------------------
// Final GEMM: out[m][o] = sum_k g_z[m][k]*Wc[o][k] + (1.1*or_b - 0.9*oi_b)[o]
// Wc on the fly: k<1024: or_w + 0.1*oi_w ; k>=1024: 0.1*or_w - oi_w.
// M=4096, N=1024, K=2048. Same permuted-smem mainloop as proj.
// ---------------------------------------------------------------------------
__global__ void __launch_bounds__(256) final_mma_kernel(
    const float* __restrict__ orw, const float* __restrict__ orb,
    const float* __restrict__ oiw, const float* __restrict__ oib,
    float* __restrict__ Outp)
{
    extern __shared__ float sm[];
    float* As = sm;
    float* Bs = sm + 2 * 128 * 36;

    const int t = threadIdx.x;
    const int w = t >> 5, lane = t & 31, g = lane >> 2, tg = lane & 3;
    const int wm = w >> 2, wn = w & 3;
    const int m0 = blockIdx.y * 128;
    const int o0 = blockIdx.x * 128;

    int lrow[4], lc4[4];
    #pragma unroll
    for (int i = 0; i < 4; i++) { int idx = i * 256 + t; lrow[i] = idx >> 3; lc4[i] = (idx & 7) * 4; }

    const float* Ag = g_z + (size_t)m0 * 2048;

    float acc[4][4][4];
    #pragma unroll
    for (int a = 0; a < 4; a++)
        #pragma unroll
        for (int b = 0; b < 4; b++)
            #pragma unroll
            for (int c = 0; c < 4; c++) acc[a][b][c] = 0.f;

    float4 pa[4], pb[4];
    #pragma unroll
    for (int i = 0; i < 4; i++) {
        pa[i] = *(const float4*)(Ag + lrow[i] * 2048 + lc4[i]);
        float4 a4 = *(const float4*)(orw + (size_t)(o0 + lrow[i]) * 1024 + lc4[i]);
        float4 b4 = *(const float4*)(oiw + (size_t)(o0 + lrow[i]) * 1024 + lc4[i]);
        pb[i] = make_float4(fmaf(0.1f, b4.x, a4.x), fmaf(0.1f, b4.y, a4.y),
                            fmaf(0.1f, b4.z, a4.z), fmaf(0.1f, b4.w, a4.w));
    }
    #pragma unroll
    for (int i = 0; i < 4; i++) {
        int q = lc4[i] >> 2;
        float* d = As + lrow[i] * 36 + q;
        d[0] = tf32f(pa[i].x); d[8] = tf32f(pa[i].y); d[16] = tf32f(pa[i].z); d[24] = tf32f(pa[i].w);
        float* e = Bs + lrow[i] * 36 + q;
        e[0] = tf32f(pb[i].x); e[8] = tf32f(pb[i].y); e[16] = tf32f(pb[i].z); e[24] = tf32f(pb[i].w);
    }
    __syncthreads();

    for (int ktile = 0; ktile < 64; ktile++) {
        const int cur = ktile & 1;
        if (ktile + 1 < 64) {
            int k0 = (ktile + 1) * 32;
            bool lo = k0 < 1024;
            int kk = lo ? k0 : (k0 - 1024);
            #pragma unroll
            for (int i = 0; i < 4; i++) {
                pa[i] = *(const float4*)(Ag + lrow[i] * 2048 + k0 + lc4[i]);
                float4 a4 = *(const float4*)(orw + (size_t)(o0 + lrow[i]) * 1024 + kk + lc4[i]);
                float4 b4 = *(const float4*)(oiw + (size_t)(o0 + lrow[i]) * 1024 + kk + lc4[i]);
                pb[i] = lo ? make_float4(fmaf(0.1f, b4.x, a4.x), fmaf(0.1f, b4.y, a4.y),
                                         fmaf(0.1f, b4.z, a4.z), fmaf(0.1f, b4.w, a4.w))
                           : make_float4(fmaf(0.1f, a4.x, -b4.x), fmaf(0.1f, a4.y, -b4.y),
                                         fmaf(0.1f, a4.z, -b4.z), fmaf(0.1f, a4.w, -b4.w));
            }
        }
        const float* Ab = As + cur * 128 * 36;
        const float* Bb = Bs + cur * 128 * 36;
        #pragma unroll
        for (int ks2 = 0; ks2 < 2; ks2++) {
            const int off = tg * 8 + 4 * ks2;
            float4 a0[4], a8[4];
            #pragma unroll
            for (int mt = 0; mt < 4; mt++) {
                const float* ap = Ab + (64 * wm + 16 * mt + g) * 36 + off;
                a0[mt] = *(const float4*)ap;
                a8[mt] = *(const float4*)(ap + 8 * 36);
            }
            #pragma unroll
            for (int nt = 0; nt < 4; nt++) {
                float4 bv = *(const float4*)(Bb + (32 * wn + 8 * nt + g) * 36 + off);
                #pragma unroll
                for (int mt = 0; mt < 4; mt++) {
                    mma8(acc[mt][nt], u32(a0[mt].x), u32(a8[mt].x), u32(a0[mt].y), u32(a8[mt].y),
                         u32(bv.x), u32(bv.y));
                    mma8(acc[mt][nt], u32(a0[mt].z), u32(a8[mt].z), u32(a0[mt].w), u32(a8[mt].w),
                         u32(bv.z), u32(bv.w));
                }
            }
        }
        if (ktile + 1 < 64) {
            float* dA = As + (1 - cur) * 128 * 36;
            float* dB = Bs + (1 - cur) * 128 * 36;
            #pragma unroll
            for (int i = 0; i < 4; i++) {
                int q = lc4[i] >> 2;
                float* d = dA + lrow[i] * 36 + q;
                d[0] = tf32f(pa[i].x); d[8] = tf32f(pa[i].y); d[16] = tf32f(pa[i].z); d[24] = tf32f(pa[i].w);
                float* e = dB + lrow[i] * 36 + q;
                e[0] = tf32f(pb[i].x); e[8] = tf32f(pb[i].y); e[16] = tf32f(pb[i].z); e[24] = tf32f(pb[i].w);
            }
        }
        __syncthreads();
    }

    const int ob = o0 + 32 * wn;
    #pragma unroll
    for (int mt = 0; mt < 4; mt++) {
        int m = m0 + 64 * wm + 16 * mt + g;
        #pragma unroll
        for (int r = 0; r < 2; r++) {
            int mm = m + 8 * r;
            float* dst = Outp + (size_t)mm * 1024;
            #pragma unroll
            for (int nt = 0; nt < 4; nt++) {
                int o = ob + 8 * nt + 2 * tg;
                float2 ra = *(const float2*)(orb + o);
                float2 rb = *(const float2*)(oib + o);
                *(float2*)(dst + o) =
                    make_float2(acc[mt][nt][2 * r + 0] + 1.1f * ra.x - 0.9f * rb.x,
                                acc[mt][nt][2 * r + 1] + 1.1f * ra.y - 0.9f * rb.y);
            }
        }
    }
}

// ---------------------------------------------------------------------------
extern "C" void kernel_launch(void* const* d_in, const int* in_sizes, int n_in,
                              void* d_out, int out_size)
{
    const float* x    = (const float*)d_in[0];
    const float* qr_w = (const float*)d_in[1];
    const float* qr_b = (const float*)d_in[2];
    const float* qi_w = (const float*)d_in[3];
    const float* qi_b = (const float*)d_in[4];
    const float* kr_w = (const float*)d_in[5];
    const float* kr_b = (const float*)d_in[6];
    const float* ki_w = (const float*)d_in[7];
    const float* ki_b = (const float*)d_in[8];
    const float* vr_w = (const float*)d_in[9];
    const float* vr_b = (const float*)d_in[10];
    const float* vi_w = (const float*)d_in[11];
    const float* vi_b = (const float*)d_in[12];
    const float* or_w = (const float*)d_in[13];
    const float* or_b = (const float*)d_in[14];
    const float* oi_w = (const float*)d_in[15];
    const float* oi_b = (const float*)d_in[16];
    float* out = (float*)d_out;

    static bool attr_set = false;
    if (!attr_set) {
        cudaFuncSetAttribute(proj_mma_kernel, cudaFuncAttributeMaxDynamicSharedMemorySize, PROJ_SMEM);
        cudaFuncSetAttribute(attn_mma_kernel, cudaFuncAttributeMaxDynamicSharedMemorySize, ATT_SMEM);
        cudaFuncSetAttribute(final_mma_kernel, cudaFuncAttributeMaxDynamicSharedMemorySize, PROJ_SMEM);
        attr_set = true;
    }

    proj_mma_kernel<<<dim3(16, 32, 3), 256, PROJ_SMEM>>>(
        x, qr_w, qr_b, qi_w, qi_b, kr_w, kr_b, ki_w, ki_b,
        vr_w, vr_b, vi_w, vi_b);

    attn_mma_kernel<<<dim3(16, 32), 256, ATT_SMEM>>>();

    final_mma_kernel<<<dim3(8, 32), 256, PROJ_SMEM>>>(or_w, or_b, oi_w, oi_b, out);
}

// round 5
// speedup vs baseline: 1.3735x; 1.3735x over previous
#include <cuda_runtime.h>
#include <cstdint>

// Problem: B=2, N=2048, C=1024, H=16, D=64
// g_q/g_k/g_v layout: [bh=32][n=2048][128], d 0..63 real, 64..127 imag (tf32-rounded)
// g_z layout: [b*2048+n][2048] = [out_r(1024) | out_i(1024)] (tf32-rounded)
// g_x, g_w:   tf32-rounded copies of x and the 6 QKV weights
// g_wc, g_fb: combined output weight (tf32-rounded) and bias

#define PROJ_SMEM (2 * 2 * 128 * 36 * 4)                              // 73728 B
#define ATT_SMEM  ((128 * 132 + 64 * 132 + 64 * 136 + 128 * 68) * 4)  // 171008 B

__device__ float g_q[32 * 2048 * 128];
__device__ float g_k[32 * 2048 * 128];
__device__ float g_v[32 * 2048 * 128];
__device__ float g_z[4096 * 2048];
__device__ float g_x[4096 * 1024];
__device__ float g_w[6 * 1024 * 1024];
__device__ float g_wc[1024 * 2048];
__device__ float g_fb[1024];

// ---------------------------------------------------------------------------
// helpers
// ---------------------------------------------------------------------------
__device__ __forceinline__ float tf32f(float x) {
    uint32_t r;
    asm("cvt.rna.tf32.f32 %0, %1;" : "=r"(r) : "f"(x));
    return __int_as_float(r);
}

__device__ __forceinline__ void mma8(float* d,
                                     uint32_t a0, uint32_t a1, uint32_t a2, uint32_t a3,
                                     uint32_t b0, uint32_t b1) {
    asm volatile(
        "mma.sync.aligned.m16n8k8.row.col.f32.tf32.tf32.f32 "
        "{%0,%1,%2,%3}, {%4,%5,%6,%7}, {%8,%9}, {%0,%1,%2,%3};"
        : "+f"(d[0]), "+f"(d[1]), "+f"(d[2]), "+f"(d[3])
        : "r"(a0), "r"(a1), "r"(a2), "r"(a3), "r"(b0), "r"(b1));
}

// sqrt on the FMA pipe: bithack rsqrt + 2 Newton iterations
__device__ __forceinline__ float sqrt_nr(float h) {
    h = fmaxf(h, 1e-24f);
    float x = __int_as_float(0x5f3759df - (__float_as_int(h) >> 1));
    float hh = 0.5f * h;
    x = x * fmaf(-hh * x, x, 1.5f);
    x = x * fmaf(-hh * x, x, 1.5f);
    return h * x;
}

// exp2 on the FMA/ALU pipes. Valid for |z| < 120.
__device__ __forceinline__ float exp2p(float z) {
    float r = z + 12582912.0f;
    int n = __float_as_int(r) - 0x4B400000;
    float f = z - (r - 12582912.0f);
    float p = 1.3333558e-3f;
    p = fmaf(p, f, 9.6181291e-3f);
    p = fmaf(p, f, 5.5504109e-2f);
    p = fmaf(p, f, 2.4022651e-1f);
    p = fmaf(p, f, 6.9314718e-1f);
    p = fmaf(p, f, 1.0f);
    return __int_as_float(__float_as_int(p) + (n << 23));
}

// ---------------------------------------------------------------------------
// Pre-round x and the 6 QKV weights into g_x / g_w (tf32).
// 10,485,760 floats = 2,621,440 float4 -> grid 10240 x 256.
// ---------------------------------------------------------------------------
__global__ void __launch_bounds__(256) prep_kernel(
    const float* __restrict__ x,
    const float* __restrict__ qrw, const float* __restrict__ qiw,
    const float* __restrict__ krw, const float* __restrict__ kiw,
    const float* __restrict__ vrw, const float* __restrict__ viw)
{
    int i4 = blockIdx.x * 256 + threadIdx.x;
    const float* src;
    float* dst;
    if (i4 < 1048576) {
        src = x + (size_t)i4 * 4;
        dst = g_x + (size_t)i4 * 4;
    } else {
        int j = i4 - 1048576;
        int wsel = j >> 18;            // 262144 float4 per weight
        int off = j & 262143;
        const float* wp;
        switch (wsel) {
            case 0: wp = qrw; break;
            case 1: wp = qiw; break;
            case 2: wp = krw; break;
            case 3: wp = kiw; break;
            case 4: wp = vrw; break;
            default: wp = viw; break;
        }
        src = wp + (size_t)off * 4;
        dst = g_w + (size_t)wsel * 1048576 + (size_t)off * 4;
    }
    float4 v = *(const float4*)src;
    v.x = tf32f(v.x); v.y = tf32f(v.y); v.z = tf32f(v.z); v.w = tf32f(v.w);
    *(float4*)dst = v;
}

// ---------------------------------------------------------------------------
// Combined output weight (tf32-rounded):
//   Wc[o][k<1024]  = or_w[o][k]      + 0.1*oi_w[o][k]
//   Wc[o][k>=1024] = 0.1*or_w[o][k'] -     oi_w[o][k']
// bias fb[o] = 1.1*or_b[o] - 0.9*oi_b[o]
// ---------------------------------------------------------------------------
__global__ void __launch_bounds__(256) make_wc_kernel(
    const float* __restrict__ orw, const float* __restrict__ oiw,
    const float* __restrict__ orb, const float* __restrict__ oib)
{
    int idx = blockIdx.x * 256 + threadIdx.x;   // float4 index over [1024][2048]
    int o = idx >> 9;
    int k = (idx & 511) << 2;
    float4 r;
    if (k < 1024) {
        float4 a = *(const float4*)(orw + (size_t)o * 1024 + k);
        float4 b = *(const float4*)(oiw + (size_t)o * 1024 + k);
        r.x = fmaf(0.1f, b.x, a.x); r.y = fmaf(0.1f, b.y, a.y);
        r.z = fmaf(0.1f, b.z, a.z); r.w = fmaf(0.1f, b.w, a.w);
    } else {
        int kk = k - 1024;
        float4 a = *(const float4*)(orw + (size_t)o * 1024 + kk);
        float4 b = *(const float4*)(oiw + (size_t)o * 1024 + kk);
        r.x = fmaf(0.1f, a.x, -b.x); r.y = fmaf(0.1f, a.y, -b.y);
        r.z = fmaf(0.1f, a.z, -b.z); r.w = fmaf(0.1f, a.w, -b.w);
    }
    r.x = tf32f(r.x); r.y = tf32f(r.y); r.z = tf32f(r.z); r.w = tf32f(r.w);
    *(float4*)(g_wc + (size_t)o * 2048 + k) = r;
    if ((idx & 511) == 0)
        g_fb[o] = 1.1f * orb[o] - 0.9f * oib[o];
}

// ---------------------------------------------------------------------------
// Input projections: blockIdx.z = 0/1/2 -> Q/K/V.
// BM=128, BN=128, BK=32, double-buffered smem, tf32 mma.
// Inputs pre-rounded (g_x, g_w) -> mainloop has no cvt.
// Epilogue writes tf32-rounded output + bias.
// ---------------------------------------------------------------------------
__global__ void __launch_bounds__(256) proj_mma_kernel(
    const float* __restrict__ qrb, const float* __restrict__ qib,
    const float* __restrict__ krb, const float* __restrict__ kib,
    const float* __restrict__ vrb, const float* __restrict__ vib)
{
    extern __shared__ float sm[];
    float* As = sm;                 // [2][128][36]
    float* Bs = sm + 2 * 128 * 36;  // [2][128][36]

    const int t = threadIdx.x;
    const int w = t >> 5, lane = t & 31, g = lane >> 2, tg = lane & 3;
    const int wm = w >> 2, wn = w & 3;
    const int z = blockIdx.z;
    const int bx = blockIdx.x;
    const int m0 = blockIdx.y * 128;
    const bool imag = bx >= 8;
    const float* bias;
    float* Out;
    if (z == 0)      { bias = imag ? qib : qrb; Out = g_q; }
    else if (z == 1) { bias = imag ? kib : krb; Out = g_k; }
    else             { bias = imag ? vib : vrb; Out = g_v; }
    const float* W = g_w + (size_t)(z * 2 + (imag ? 1 : 0)) * 1024 * 1024;
    const int o0 = (bx & 7) * 128;

    int lrow[4], lc4[4];
    #pragma unroll
    for (int i = 0; i < 4; i++) { int idx = i * 256 + t; lrow[i] = idx >> 3; lc4[i] = (idx & 7) * 4; }

    const float* Ag = g_x + (size_t)m0 * 1024;
    const float* Bg = W + (size_t)o0 * 1024;

    float acc[4][4][4];
    #pragma unroll
    for (int a = 0; a < 4; a++)
        #pragma unroll
        for (int b = 0; b < 4; b++)
            #pragma unroll
            for (int c = 0; c < 4; c++) acc[a][b][c] = 0.f;

    float4 pa[4], pb[4];
    #pragma unroll
    for (int i = 0; i < 4; i++) {
        pa[i] = *(const float4*)(Ag + lrow[i] * 1024 + lc4[i]);
        pb[i] = *(const float4*)(Bg + lrow[i] * 1024 + lc4[i]);
    }
    #pragma unroll
    for (int i = 0; i < 4; i++) {
        *(float4*)(As + lrow[i] * 36 + lc4[i]) = pa[i];
        *(float4*)(Bs + lrow[i] * 36 + lc4[i]) = pb[i];
    }
    __syncthreads();

    for (int ktile = 0; ktile < 32; ktile++) {
        const int cur = ktile & 1;
        if (ktile + 1 < 32) {
            int k0 = (ktile + 1) * 32;
            #pragma unroll
            for (int i = 0; i < 4; i++) {
                pa[i] = *(const float4*)(Ag + lrow[i] * 1024 + k0 + lc4[i]);
                pb[i] = *(const float4*)(Bg + lrow[i] * 1024 + k0 + lc4[i]);
            }
        }
        const float* Ab = As + cur * 128 * 36;
        const float* Bb = Bs + cur * 128 * 36;
        #pragma unroll
        for (int ks = 0; ks < 4; ks++) {
            const int col = 8 * ks + tg;
            uint32_t a[4][4];
            #pragma unroll
            for (int mt = 0; mt < 4; mt++) {
                const float* ap = Ab + (64 * wm + 16 * mt + g) * 36;
                a[mt][0] = __float_as_uint(ap[col]);
                a[mt][1] = __float_as_uint(ap[8 * 36 + col]);
                a[mt][2] = __float_as_uint(ap[col + 4]);
                a[mt][3] = __float_as_uint(ap[8 * 36 + col + 4]);
            }
            #pragma unroll
            for (int nt = 0; nt < 4; nt++) {
                const float* bp = Bb + (32 * wn + 8 * nt + g) * 36;
                uint32_t b0 = __float_as_uint(bp[col]);
                uint32_t b1 = __float_as_uint(bp[col + 4]);
                #pragma unroll
                for (int mt = 0; mt < 4; mt++)
                    mma8(acc[mt][nt], a[mt][0], a[mt][1], a[mt][2], a[mt][3], b0, b1);
            }
        }
        if (ktile + 1 < 32) {
            float* dA = As + (1 - cur) * 128 * 36;
            float* dB = Bs + (1 - cur) * 128 * 36;
            #pragma unroll
            for (int i = 0; i < 4; i++) {
                *(float4*)(dA + lrow[i] * 36 + lc4[i]) = pa[i];
                *(float4*)(dB + lrow[i] * 36 + lc4[i]) = pb[i];
            }
        }
        __syncthreads();
    }

    // epilogue: scatter tf32-rounded (acc + bias) into [bh][n][128]
    const int part = imag ? 1 : 0;
    const int ob = o0 + 32 * wn;
    const int hh = ob >> 6;
    #pragma unroll
    for (int mt = 0; mt < 4; mt++) {
        int m = m0 + 64 * wm + 16 * mt + g;
        #pragma unroll
        for (int r = 0; r < 2; r++) {
            int mm = m + 8 * r;
            int b_ = mm >> 11, nn = mm & 2047;
            float* dst = Out + ((size_t)(b_ * 16 + hh) * 2048 + nn) * 128 + part * 64;
            #pragma unroll
            for (int nt = 0; nt < 4; nt++) {
                int o = ob + 8 * nt + 2 * tg;
                float2 bv = *(const float2*)(bias + o);
                *(float2*)(dst + (o & 63)) =
                    make_float2(tf32f(acc[mt][nt][2 * r + 0] + bv.x),
                                tf32f(acc[mt][nt][2 * r + 1] + bv.y));
            }
        }
    }
}

// ---------------------------------------------------------------------------
// Fused complex-magnitude attention, tf32 mma + FMA-pipe softmax.
// Block = 128 queries x one bh; 8 warps, 16 query rows each; 64-key tiles.
// Inputs pre-rounded -> tile loads are straight float4 copies.
// Fixed-shift softmax: p = exp2(0.18034*s - 11.5416) == exp(0.125*|s| - 8).
// Writes tf32-rounded merged-head output into g_z.
// ---------------------------------------------------------------------------
__global__ void __launch_bounds__(256) attn_mma_kernel()
{
    extern __shared__ float sm[];
    float* Qs = sm;                  // [128][132]
    float* Ks = Qs + 128 * 132;      // [64][132]
    float* Vs = Ks + 64 * 132;       // [64][136]
    float* Ps = Vs + 64 * 136;       // [128][68]

    const int t = threadIdx.x;
    const int w = t >> 5, lane = t & 31, g = lane >> 2, tg = lane & 3;
    const int bh = blockIdx.y;
    const int q0 = blockIdx.x * 128;

    const float* Qg = g_q + ((size_t)bh * 2048 + q0) * 128;
    const float* Kg = g_k + (size_t)bh * 2048 * 128;
    const float* Vg = g_v + (size_t)bh * 2048 * 128;

    #pragma unroll
    for (int i = 0; i < 16; i++) {
        int idx = i * 256 + t;
        int row = idx >> 5, c4 = (idx & 31) * 4;
        *(float4*)(Qs + row * 132 + c4) = *(const float4*)(Qg + row * 128 + c4);
    }

    float O[16][4];
    #pragma unroll
    for (int i = 0; i < 16; i++) { O[i][0] = 0.f; O[i][1] = 0.f; O[i][2] = 0.f; O[i][3] = 0.f; }
    float l0 = 0.f, l1 = 0.f;

    const int qrow = 16 * w;
    const float K1 = 0.18033688f;   // 0.125 * log2(e)
    const float K2 = -11.541560f;   // -8 * log2(e)

    for (int kt = 0; kt < 32; kt++) {
        __syncthreads();   // previous tile's readers of Ks/Vs done (Qs ready on 1st)
        const float* Kt = Kg + (size_t)kt * 64 * 128;
        const float* Vt = Vg + (size_t)kt * 64 * 128;
        #pragma unroll
        for (int i = 0; i < 8; i++) {
            int idx = i * 256 + t;
            int row = idx >> 5, c4 = (idx & 31) * 4;
            *(float4*)(Ks + row * 132 + c4) = *(const float4*)(Kt + row * 128 + c4);
            *(float4*)(Vs + row * 136 + c4) = *(const float4*)(Vt + row * 128 + c4);
        }
        __syncthreads();

        float Sr[8][4], Si[8][4];
        #pragma unroll
        for (int i = 0; i < 8; i++) {
            Sr[i][0] = 0.f; Sr[i][1] = 0.f; Sr[i][2] = 0.f; Sr[i][3] = 0.f;
            Si[i][0] = 0.f; Si[i][1] = 0.f; Si[i][2] = 0.f; Si[i][3] = 0.f;
        }

        #pragma unroll 2
        for (int ks = 0; ks < 8; ks++) {
            const int col = 8 * ks + tg;
            const float* q0p = Qs + (qrow + g) * 132;
            const float* q8p = Qs + (qrow + g + 8) * 132;
            uint32_t ar0 = __float_as_uint(q0p[col]);
            uint32_t ar1 = __float_as_uint(q8p[col]);
            uint32_t ar2 = __float_as_uint(q0p[col + 4]);
            uint32_t ar3 = __float_as_uint(q8p[col + 4]);
            uint32_t ai0 = __float_as_uint(q0p[col + 64]);
            uint32_t ai1 = __float_as_uint(q8p[col + 64]);
            uint32_t ai2 = __float_as_uint(q0p[col + 68]);
            uint32_t ai3 = __float_as_uint(q8p[col + 68]);
            uint32_t nr0 = ar0 ^ 0x80000000u, nr1 = ar1 ^ 0x80000000u;
            uint32_t nr2 = ar2 ^ 0x80000000u, nr3 = ar3 ^ 0x80000000u;
            #pragma unroll
            for (int nt = 0; nt < 8; nt++) {
                const float* kp = Ks + (8 * nt + g) * 132 + col;
                uint32_t br0 = __float_as_uint(kp[0]);
                uint32_t br1 = __float_as_uint(kp[4]);
                uint32_t bi0 = __float_as_uint(kp[64]);
                uint32_t bi1 = __float_as_uint(kp[68]);
                mma8(Sr[nt], ar0, ar1, ar2, ar3, br0, br1);  // qr.kr
                mma8(Sr[nt], ai0, ai1, ai2, ai3, bi0, bi1);  // + qi.ki
                mma8(Si[nt], ai0, ai1, ai2, ai3, br0, br1);  // qi.kr
                mma8(Si[nt], nr0, nr1, nr2, nr3, bi0, bi1);  // - qr.ki
            }
        }

        // magnitude + exp on FMA/ALU pipes; accumulate l; store P
        #pragma unroll
        for (int nt = 0; nt < 8; nt++) {
            float h0 = fmaf(Si[nt][0], Si[nt][0], Sr[nt][0] * Sr[nt][0]);
            float h1 = fmaf(Si[nt][1], Si[nt][1], Sr[nt][1] * Sr[nt][1]);
            float h2 = fmaf(Si[nt][2], Si[nt][2], Sr[nt][2] * Sr[nt][2]);
            float h3 = fmaf(Si[nt][3], Si[nt][3], Sr[nt][3] * Sr[nt][3]);
            float p0 = exp2p(fmaf(sqrt_nr(h0), K1, K2));
            float p1 = exp2p(fmaf(sqrt_nr(h1), K1, K2));
            float p2 = exp2p(fmaf(sqrt_nr(h2), K1, K2));
            float p3 = exp2p(fmaf(sqrt_nr(h3), K1, K2));
            l0 += p0 + p1;
            l1 += p2 + p3;
            *(float2*)(Ps + (qrow + g) * 68 + 8 * nt + 2 * tg) = make_float2(tf32f(p0), tf32f(p1));
            *(float2*)(Ps + (qrow + g + 8) * 68 + 8 * nt + 2 * tg) = make_float2(tf32f(p2), tf32f(p3));
        }
        __syncwarp();   // each warp reads only its own 16 P rows

        // O += P @ [vr|vi]
        #pragma unroll 2
        for (int ks = 0; ks < 8; ks++) {
            const int pcol = 8 * ks + tg;
            uint32_t a0 = __float_as_uint(Ps[(qrow + g) * 68 + pcol]);
            uint32_t a1 = __float_as_uint(Ps[(qrow + g + 8) * 68 + pcol]);
            uint32_t a2 = __float_as_uint(Ps[(qrow + g) * 68 + pcol + 4]);
            uint32_t a3 = __float_as_uint(Ps[(qrow + g + 8) * 68 + pcol + 4]);
            const float* v0p = Vs + (8 * ks + tg) * 136 + g;
            const float* v1p = Vs + (8 * ks + tg + 4) * 136 + g;
            #pragma unroll
            for (int nt = 0; nt < 16; nt++) {
                uint32_t b0 = __float_as_uint(v0p[8 * nt]);
                uint32_t b1 = __float_as_uint(v1p[8 * nt]);
                mma8(O[nt], a0, a1, a2, a3, b0, b1);
            }
        }
    }

    // epilogue: divide by row sums, write tf32-rounded merged-head layout
    l0 += __shfl_xor_sync(0xffffffffu, l0, 1);
    l0 += __shfl_xor_sync(0xffffffffu, l0, 2);
    l1 += __shfl_xor_sync(0xffffffffu, l1, 1);
    l1 += __shfl_xor_sync(0xffffffffu, l1, 2);
    const float inv0 = 1.f / l0, inv1 = 1.f / l1;

    const int b_ = bh >> 4, hh = bh & 15;
    const int q = q0 + qrow + g;
    float* dst0 = g_z + (size_t)(b_ * 2048 + q) * 2048;
    float* dst1 = g_z + (size_t)(b_ * 2048 + q + 8) * 2048;
    #pragma unroll
    for (int nt = 0; nt < 16; nt++) {
        int d0 = 8 * nt + 2 * tg;
        int col = (d0 >> 6) * 1024 + hh * 64 + (d0 & 63);
        *(float2*)(dst0 + col) = make_float2(tf32f(O[nt][0] * inv0), tf32f(O[nt][1] * inv0));
        *(float2*)(dst1 + col) = make_float2(tf32f(O[nt][2] * inv1), tf32f(O[nt][3] * inv1));
    }
}

// ---------------------------------------------------------------------------
// Final GEMM: out[m][o] = sum_k g_z[m][k]*g_wc[o][k] + g_fb[o]
// Both inputs pre-rounded tf32 -> no cvt anywhere.
// M=4096, N=1024, K=2048.
// ---------------------------------------------------------------------------
__global__ void __launch_bounds__(256) final_mma_kernel(float* __restrict__ Outp)
{
    extern __shared__ float sm[];
    float* As = sm;
    float* Bs = sm + 2 * 128 * 36;

    const int t = threadIdx.x;
    const int w = t >> 5, lane = t & 31, g = lane >> 2, tg = lane & 3;
    const int wm = w >> 2, wn = w & 3;
    const int m0 = blockIdx.y * 128;
    const int o0 = blockIdx.x * 128;

    int lrow[4], lc4[4];
    #pragma unroll
    for (int i = 0; i < 4; i++) { int idx = i * 256 + t; lrow[i] = idx >> 3; lc4[i] = (idx & 7) * 4; }

    const float* Ag = g_z + (size_t)m0 * 2048;
    const float* Bg = g_wc + (size_t)o0 * 2048;

    float acc[4][4][4];
    #pragma unroll
    for (int a = 0; a < 4; a++)
        #pragma unroll
        for (int b = 0; b < 4; b++)
            #pragma unroll
            for (int c = 0; c < 4; c++) acc[a][b][c] = 0.f;

    float4 pa[4], pb[4];
    #pragma unroll
    for (int i = 0; i < 4; i++) {
        pa[i] = *(const float4*)(Ag + lrow[i] * 2048 + lc4[i]);
        pb[i] = *(const float4*)(Bg + lrow[i] * 2048 + lc4[i]);
    }
    #pragma unroll
    for (int i = 0; i < 4; i++) {
        *(float4*)(As + lrow[i] * 36 + lc4[i]) = pa[i];
        *(float4*)(Bs + lrow[i] * 36 + lc4[i]) = pb[i];
    }
    __syncthreads();

    for (int ktile = 0; ktile < 64; ktile++) {
        const int cur = ktile & 1;
        if (ktile + 1 < 64) {
            int k0 = (ktile + 1) * 32;
            #pragma unroll
            for (int i = 0; i < 4; i++) {
                pa[i] = *(const float4*)(Ag + lrow[i] * 2048 + k0 + lc4[i]);
                pb[i] = *(const float4*)(Bg + lrow[i] * 2048 + k0 + lc4[i]);
            }
        }
        const float* Ab = As + cur * 128 * 36;
        const float* Bb = Bs + cur * 128 * 36;
        #pragma unroll
        for (int ks = 0; ks < 4; ks++) {
            const int col = 8 * ks + tg;
            uint32_t a[4][4];
            #pragma unroll
            for (int mt = 0; mt < 4; mt++) {
                const float* ap = Ab + (64 * wm + 16 * mt + g) * 36;
                a[mt][0] = __float_as_uint(ap[col]);
                a[mt][1] = __float_as_uint(ap[8 * 36 + col]);
                a[mt][2] = __float_as_uint(ap[col + 4]);
                a[mt][3] = __float_as_uint(ap[8 * 36 + col + 4]);
            }
            #pragma unroll
            for (int nt = 0; nt < 4; nt++) {
                const float* bp = Bb + (32 * wn + 8 * nt + g) * 36;
                uint32_t b0 = __float_as_uint(bp[col]);
                uint32_t b1 = __float_as_uint(bp[col + 4]);
                #pragma unroll
                for (int mt = 0; mt < 4; mt++)
                    mma8(acc[mt][nt], a[mt][0], a[mt][1], a[mt][2], a[mt][3], b0, b1);
            }
        }
        if (ktile + 1 < 64) {
            float* dA = As + (1 - cur) * 128 * 36;
            float* dB = Bs + (1 - cur) * 128 * 36;
            #pragma unroll
            for (int i = 0; i < 4; i++) {
                *(float4*)(dA + lrow[i] * 36 + lc4[i]) = pa[i];
                *(float4*)(dB + lrow[i] * 36 + lc4[i]) = pb[i];
            }
        }
        __syncthreads();
    }

    const int ob = o0 + 32 * wn;
    #pragma unroll
    for (int mt = 0; mt < 4; mt++) {
        int m = m0 + 64 * wm + 16 * mt + g;
        #pragma unroll
        for (int r = 0; r < 2; r++) {
            int mm = m + 8 * r;
            float* dst = Outp + (size_t)mm * 1024;
            #pragma unroll
            for (int nt = 0; nt < 4; nt++) {
                int o = ob + 8 * nt + 2 * tg;
                float2 fb = *(const float2*)(g_fb + o);
                *(float2*)(dst + o) =
                    make_float2(acc[mt][nt][2 * r + 0] + fb.x,
                                acc[mt][nt][2 * r + 1] + fb.y);
            }
        }
    }
}

// ---------------------------------------------------------------------------
extern "C" void kernel_launch(void* const* d_in, const int* in_sizes, int n_in,
                              void* d_out, int out_size)
{
    const float* x    = (const float*)d_in[0];
    const float* qr_w = (const float*)d_in[1];
    const float* qr_b = (const float*)d_in[2];
    const float* qi_w = (const float*)d_in[3];
    const float* qi_b = (const float*)d_in[4];
    const float* kr_w = (const float*)d_in[5];
    const float* kr_b = (const float*)d_in[6];
    const float* ki_w = (const float*)d_in[7];
    const float* ki_b = (const float*)d_in[8];
    const float* vr_w = (const float*)d_in[9];
    const float* vr_b = (const float*)d_in[10];
    const float* vi_w = (const float*)d_in[11];
    const float* vi_b = (const float*)d_in[12];
    const float* or_w = (const float*)d_in[13];
    const float* or_b = (const float*)d_in[14];
    const float* oi_w = (const float*)d_in[15];
    const float* oi_b = (const float*)d_in[16];
    float* out = (float*)d_out;

    static bool attr_set = false;
    if (!attr_set) {
        cudaFuncSetAttribute(proj_mma_kernel, cudaFuncAttributeMaxDynamicSharedMemorySize, PROJ_SMEM);
        cudaFuncSetAttribute(attn_mma_kernel, cudaFuncAttributeMaxDynamicSharedMemorySize, ATT_SMEM);
        cudaFuncSetAttribute(final_mma_kernel, cudaFuncAttributeMaxDynamicSharedMemorySize, PROJ_SMEM);
        attr_set = true;
    }

    prep_kernel<<<10240, 256>>>(x, qr_w, qi_w, kr_w, ki_w, vr_w, vi_w);
    make_wc_kernel<<<2048, 256>>>(or_w, oi_w, or_b, oi_b);

    proj_mma_kernel<<<dim3(16, 32, 3), 256, PROJ_SMEM>>>(
        qr_b, qi_b, kr_b, ki_b, vr_b, vi_b);

    attn_mma_kernel<<<dim3(16, 32), 256, ATT_SMEM>>>();

    final_mma_kernel<<<dim3(8, 32), 256, PROJ_SMEM>>>(out);
}

// round 6
// speedup vs baseline: 1.3798x; 1.0045x over previous
#include <cuda_runtime.h>
#include <cstdint>

// Problem: B=2, N=2048, C=1024, H=16, D=64
// g_q/g_k/g_v: [bh=32][n=2048][128], d 0..63 real, 64..127 imag (tf32-rounded)
// g_z: [b*2048+n][2048] = [out_r(1024) | out_i(1024)] (tf32-rounded)
// g_x, g_w: tf32-rounded copies of x and the 6 QKV weights
// g_wc, g_fb: combined output weight (tf32-rounded) and bias

#define PROJ_SMEM (2 * 2 * 128 * 36 * 4)                      // 73728 B
#define ATT_SMEM  ((128 * 132 + 128 * 136 + 128 * 68) * 4)    // 172032 B

__device__ float g_q[32 * 2048 * 128];
__device__ float g_k[32 * 2048 * 128];
__device__ float g_v[32 * 2048 * 128];
__device__ float g_z[4096 * 2048];
__device__ float g_x[4096 * 1024];
__device__ float g_w[6 * 1024 * 1024];
__device__ float g_wc[1024 * 2048];
__device__ float g_fb[1024];

// ---------------------------------------------------------------------------
// helpers
// ---------------------------------------------------------------------------
__device__ __forceinline__ float tf32f(float x) {
    uint32_t r;
    asm("cvt.rna.tf32.f32 %0, %1;" : "=r"(r) : "f"(x));
    return __int_as_float(r);
}
__device__ __forceinline__ uint32_t fu(float x) { return __float_as_uint(x); }

__device__ __forceinline__ void mma8(float* d,
                                     uint32_t a0, uint32_t a1, uint32_t a2, uint32_t a3,
                                     uint32_t b0, uint32_t b1) {
    asm volatile(
        "mma.sync.aligned.m16n8k8.row.col.f32.tf32.tf32.f32 "
        "{%0,%1,%2,%3}, {%4,%5,%6,%7}, {%8,%9}, {%0,%1,%2,%3};"
        : "+f"(d[0]), "+f"(d[1]), "+f"(d[2]), "+f"(d[3])
        : "r"(a0), "r"(a1), "r"(a2), "r"(a3), "r"(b0), "r"(b1));
}

__device__ __forceinline__ void cpa16(uint32_t dst, const float* src) {
    asm volatile("cp.async.cg.shared.global [%0], [%1], 16;" :: "r"(dst), "l"(src));
}
#define CP_COMMIT() asm volatile("cp.async.commit_group;")
#define CP_WAIT0()  asm volatile("cp.async.wait_group 0;")

// sqrt on the FMA pipe: bithack rsqrt + 2 Newton iterations
__device__ __forceinline__ float sqrt_nr(float h) {
    h = fmaxf(h, 1e-24f);
    float x = __int_as_float(0x5f3759df - (__float_as_int(h) >> 1));
    float hh = 0.5f * h;
    x = x * fmaf(-hh * x, x, 1.5f);
    x = x * fmaf(-hh * x, x, 1.5f);
    return h * x;
}

// exp2 on the FMA/ALU pipes. Valid for |z| < 120.
__device__ __forceinline__ float exp2p(float z) {
    float r = z + 12582912.0f;
    int n = __float_as_int(r) - 0x4B400000;
    float f = z - (r - 12582912.0f);
    float p = 1.3333558e-3f;
    p = fmaf(p, f, 9.6181291e-3f);
    p = fmaf(p, f, 5.5504109e-2f);
    p = fmaf(p, f, 2.4022651e-1f);
    p = fmaf(p, f, 6.9314718e-1f);
    p = fmaf(p, f, 1.0f);
    return __int_as_float(__float_as_int(p) + (n << 23));
}

// ---------------------------------------------------------------------------
// Pre-round x and the 6 QKV weights into g_x / g_w (tf32).
// ---------------------------------------------------------------------------
__global__ void __launch_bounds__(256) prep_kernel(
    const float* __restrict__ x,
    const float* __restrict__ qrw, const float* __restrict__ qiw,
    const float* __restrict__ krw, const float* __restrict__ kiw,
    const float* __restrict__ vrw, const float* __restrict__ viw)
{
    int i4 = blockIdx.x * 256 + threadIdx.x;
    const float* src;
    float* dst;
    if (i4 < 1048576) {
        src = x + (size_t)i4 * 4;
        dst = g_x + (size_t)i4 * 4;
    } else {
        int j = i4 - 1048576;
        int wsel = j >> 18;
        int off = j & 262143;
        const float* wp;
        switch (wsel) {
            case 0: wp = qrw; break;
            case 1: wp = qiw; break;
            case 2: wp = krw; break;
            case 3: wp = kiw; break;
            case 4: wp = vrw; break;
            default: wp = viw; break;
        }
        src = wp + (size_t)off * 4;
        dst = g_w + (size_t)wsel * 1048576 + (size_t)off * 4;
    }
    float4 v = *(const float4*)src;
    v.x = tf32f(v.x); v.y = tf32f(v.y); v.z = tf32f(v.z); v.w = tf32f(v.w);
    *(float4*)dst = v;
}

// ---------------------------------------------------------------------------
// Combined output weight (tf32-rounded) + bias.
// ---------------------------------------------------------------------------
__global__ void __launch_bounds__(256) make_wc_kernel(
    const float* __restrict__ orw, const float* __restrict__ oiw,
    const float* __restrict__ orb, const float* __restrict__ oib)
{
    int idx = blockIdx.x * 256 + threadIdx.x;
    int o = idx >> 9;
    int k = (idx & 511) << 2;
    float4 r;
    if (k < 1024) {
        float4 a = *(const float4*)(orw + (size_t)o * 1024 + k);
        float4 b = *(const float4*)(oiw + (size_t)o * 1024 + k);
        r.x = fmaf(0.1f, b.x, a.x); r.y = fmaf(0.1f, b.y, a.y);
        r.z = fmaf(0.1f, b.z, a.z); r.w = fmaf(0.1f, b.w, a.w);
    } else {
        int kk = k - 1024;
        float4 a = *(const float4*)(orw + (size_t)o * 1024 + kk);
        float4 b = *(const float4*)(oiw + (size_t)o * 1024 + kk);
        r.x = fmaf(0.1f, a.x, -b.x); r.y = fmaf(0.1f, a.y, -b.y);
        r.z = fmaf(0.1f, a.z, -b.z); r.w = fmaf(0.1f, a.w, -b.w);
    }
    r.x = tf32f(r.x); r.y = tf32f(r.y); r.z = tf32f(r.z); r.w = tf32f(r.w);
    *(float4*)(g_wc + (size_t)o * 2048 + k) = r;
    if ((idx & 511) == 0)
        g_fb[o] = 1.1f * orb[o] - 0.9f * oib[o];
}

// ---------------------------------------------------------------------------
// Input projections: blockIdx.z = 0/1/2 -> Q/K/V.
// BM=128, BN=128, BK=32, cp.async double-buffered smem, tf32 mma.
// launch_bounds(256,2): <=128 regs -> 2 CTAs/SM.
// ---------------------------------------------------------------------------
__global__ void __launch_bounds__(256, 2) proj_mma_kernel(
    const float* __restrict__ qrb, const float* __restrict__ qib,
    const float* __restrict__ krb, const float* __restrict__ kib,
    const float* __restrict__ vrb, const float* __restrict__ vib)
{
    extern __shared__ float sm[];
    float* As = sm;                 // [2][128][36]
    float* Bs = sm + 2 * 128 * 36;  // [2][128][36]
    const uint32_t as_u = (uint32_t)__cvta_generic_to_shared(As);
    const uint32_t bs_u = (uint32_t)__cvta_generic_to_shared(Bs);

    const int t = threadIdx.x;
    const int w = t >> 5, lane = t & 31, g = lane >> 2, tg = lane & 3;
    const int wm = w >> 2, wn = w & 3;
    const int z = blockIdx.z;
    const int bx = blockIdx.x;
    const int m0 = blockIdx.y * 128;
    const bool imag = bx >= 8;
    const float* bias;
    float* Out;
    if (z == 0)      { bias = imag ? qib : qrb; Out = g_q; }
    else if (z == 1) { bias = imag ? kib : krb; Out = g_k; }
    else             { bias = imag ? vib : vrb; Out = g_v; }
    const float* W = g_w + (size_t)(z * 2 + (imag ? 1 : 0)) * 1024 * 1024;
    const int o0 = (bx & 7) * 128;

    const int lrow = t >> 1;            // 4 rows per thread spaced 128... no:
    // 1024 float4 per tile / 256 threads = 4 each
    int lr[4], lc[4];
    #pragma unroll
    for (int i = 0; i < 4; i++) { int idx = i * 256 + t; lr[i] = idx >> 3; lc[i] = (idx & 7) * 4; }
    (void)lrow;

    const float* Ag = g_x + (size_t)m0 * 1024;
    const float* Bg = W + (size_t)o0 * 1024;

    auto loadAB = [&](int k0, int buf) {
        const int boff = buf * 128 * 36;
        #pragma unroll
        for (int i = 0; i < 4; i++) {
            cpa16(as_u + (boff + lr[i] * 36 + lc[i]) * 4, Ag + lr[i] * 1024 + k0 + lc[i]);
            cpa16(bs_u + (boff + lr[i] * 36 + lc[i]) * 4, Bg + lr[i] * 1024 + k0 + lc[i]);
        }
        CP_COMMIT();
    };

    float acc[4][4][4];
    #pragma unroll
    for (int a = 0; a < 4; a++)
        #pragma unroll
        for (int b = 0; b < 4; b++)
            #pragma unroll
            for (int c = 0; c < 4; c++) acc[a][b][c] = 0.f;

    loadAB(0, 0);

    for (int kt = 0; kt < 32; kt++) {
        CP_WAIT0();
        __syncthreads();
        if (kt + 1 < 32) loadAB((kt + 1) * 32, (kt + 1) & 1);
        const float* Ab = As + (kt & 1) * 128 * 36;
        const float* Bb = Bs + (kt & 1) * 128 * 36;
        #pragma unroll
        for (int ks = 0; ks < 4; ks++) {
            const int col = 8 * ks + tg;
            uint32_t a[4][4];
            #pragma unroll
            for (int mt = 0; mt < 4; mt++) {
                const float* ap = Ab + (64 * wm + 16 * mt + g) * 36;
                a[mt][0] = fu(ap[col]);
                a[mt][1] = fu(ap[8 * 36 + col]);
                a[mt][2] = fu(ap[col + 4]);
                a[mt][3] = fu(ap[8 * 36 + col + 4]);
            }
            #pragma unroll
            for (int nt = 0; nt < 4; nt++) {
                const float* bp = Bb + (32 * wn + 8 * nt + g) * 36;
                uint32_t b0 = fu(bp[col]);
                uint32_t b1 = fu(bp[col + 4]);
                #pragma unroll
                for (int mt = 0; mt < 4; mt++)
                    mma8(acc[mt][nt], a[mt][0], a[mt][1], a[mt][2], a[mt][3], b0, b1);
            }
        }
    }

    // epilogue: scatter tf32-rounded (acc + bias) into [bh][n][128]
    const int part = imag ? 1 : 0;
    const int ob = o0 + 32 * wn;
    const int hh = ob >> 6;
    #pragma unroll
    for (int mt = 0; mt < 4; mt++) {
        int m = m0 + 64 * wm + 16 * mt + g;
        #pragma unroll
        for (int r = 0; r < 2; r++) {
            int mm = m + 8 * r;
            int b_ = mm >> 11, nn = mm & 2047;
            float* dst = Out + ((size_t)(b_ * 16 + hh) * 2048 + nn) * 128 + part * 64;
            #pragma unroll
            for (int nt = 0; nt < 4; nt++) {
                int o = ob + 8 * nt + 2 * tg;
                float2 bv = *(const float2*)(bias + o);
                *(float2*)(dst + (o & 63)) =
                    make_float2(tf32f(acc[mt][nt][2 * r + 0] + bv.x),
                                tf32f(acc[mt][nt][2 * r + 1] + bv.y));
            }
        }
    }
}

// ---------------------------------------------------------------------------
// Fused complex-magnitude attention, tf32 mma + FMA-pipe softmax.
// Block = 128 queries x one bh; 8 warps, 16 query rows each; 64-key tiles.
// Q fragments live in registers (loaded once); K/V cp.async double-buffered.
// Fixed-shift softmax: p = exp2(0.18034*s - 11.5416) == exp(0.125*|s| - 8).
// ---------------------------------------------------------------------------
__global__ void __launch_bounds__(256) attn_mma_kernel()
{
    extern __shared__ float sm[];
    float* Ks0 = sm;                   // [64][132]
    float* Ks1 = sm + 64 * 132;        // [64][132]
    float* Vs0 = sm + 128 * 132;       // [64][136]
    float* Vs1 = Vs0 + 64 * 136;       // [64][136]
    float* Ps  = Vs1 + 64 * 136;       // [128][68]
    const uint32_t ks0_u = (uint32_t)__cvta_generic_to_shared(Ks0);
    const uint32_t ks1_u = (uint32_t)__cvta_generic_to_shared(Ks1);
    const uint32_t vs0_u = (uint32_t)__cvta_generic_to_shared(Vs0);
    const uint32_t vs1_u = (uint32_t)__cvta_generic_to_shared(Vs1);

    const int t = threadIdx.x;
    const int w = t >> 5, lane = t & 31, g = lane >> 2, tg = lane & 3;
    const int bh = blockIdx.y;
    const int q0 = blockIdx.x * 128;
    const int qrow = 16 * w;

    const float* Qg = g_q + ((size_t)bh * 2048 + q0) * 128;
    const float* Kg = g_k + (size_t)bh * 2048 * 128;
    const float* Vg = g_v + (size_t)bh * 2048 * 128;

    // stage Q through the K double-buffer area (128 rows x 132 = both buffers)
    #pragma unroll
    for (int i = 0; i < 16; i++) {
        int idx = i * 256 + t;
        int row = idx >> 5, c4 = (idx & 31) * 4;
        cpa16(ks0_u + (row * 132 + c4) * 4, Qg + row * 128 + c4);
    }
    CP_COMMIT();
    CP_WAIT0();
    __syncthreads();

    // Q fragments -> registers (pattern is identical for every k-tile)
    float qr[8][4], qi[8][4];
    #pragma unroll
    for (int ks = 0; ks < 8; ks++) {
        const int col = 8 * ks + tg;
        const float* r0 = Ks0 + (qrow + g) * 132;
        const float* r8 = Ks0 + (qrow + g + 8) * 132;
        qr[ks][0] = r0[col];      qr[ks][1] = r8[col];
        qr[ks][2] = r0[col + 4];  qr[ks][3] = r8[col + 4];
        qi[ks][0] = r0[col + 64]; qi[ks][1] = r8[col + 64];
        qi[ks][2] = r0[col + 68]; qi[ks][3] = r8[col + 68];
    }
    __syncthreads();   // everyone done reading staged Q before K(0) overwrites

    auto loadKV = [&](int kt, uint32_t ku, uint32_t vu) {
        const float* Kt = Kg + (size_t)kt * 64 * 128;
        const float* Vt = Vg + (size_t)kt * 64 * 128;
        #pragma unroll
        for (int i = 0; i < 8; i++) {
            int idx = i * 256 + t;
            int row = idx >> 5, c4 = (idx & 31) * 4;
            cpa16(ku + (row * 132 + c4) * 4, Kt + row * 128 + c4);
            cpa16(vu + (row * 136 + c4) * 4, Vt + row * 128 + c4);
        }
        CP_COMMIT();
    };

    float O[16][4];
    #pragma unroll
    for (int i = 0; i < 16; i++) { O[i][0] = 0.f; O[i][1] = 0.f; O[i][2] = 0.f; O[i][3] = 0.f; }
    float l0 = 0.f, l1 = 0.f;

    const float K1 = 0.18033688f;   // 0.125 * log2(e)
    const float K2 = -11.541560f;   // -8 * log2(e)

    loadKV(0, ks0_u, vs0_u);

    for (int kt = 0; kt < 32; kt++) {
        CP_WAIT0();
        __syncthreads();
        if (kt + 1 < 32)
            loadKV(kt + 1, (kt & 1) ? ks0_u : ks1_u, (kt & 1) ? vs0_u : vs1_u);
        const float* Kb = (kt & 1) ? Ks1 : Ks0;
        const float* Vb = (kt & 1) ? Vs1 : Vs0;

        float Sr[8][4], Si[8][4];
        #pragma unroll
        for (int i = 0; i < 8; i++) {
            Sr[i][0] = 0.f; Sr[i][1] = 0.f; Sr[i][2] = 0.f; Sr[i][3] = 0.f;
            Si[i][0] = 0.f; Si[i][1] = 0.f; Si[i][2] = 0.f; Si[i][3] = 0.f;
        }

        #pragma unroll 2
        for (int ks = 0; ks < 8; ks++) {
            const int col = 8 * ks + tg;
            const uint32_t ar0 = fu(qr[ks][0]), ar1 = fu(qr[ks][1]);
            const uint32_t ar2 = fu(qr[ks][2]), ar3 = fu(qr[ks][3]);
            const uint32_t ai0 = fu(qi[ks][0]), ai1 = fu(qi[ks][1]);
            const uint32_t ai2 = fu(qi[ks][2]), ai3 = fu(qi[ks][3]);
            const uint32_t nr0 = ar0 ^ 0x80000000u, nr1 = ar1 ^ 0x80000000u;
            const uint32_t nr2 = ar2 ^ 0x80000000u, nr3 = ar3 ^ 0x80000000u;
            #pragma unroll
            for (int nt = 0; nt < 8; nt++) {
                const float* kp = Kb + (8 * nt + g) * 132 + col;
                uint32_t br0 = fu(kp[0]);
                uint32_t br1 = fu(kp[4]);
                uint32_t bi0 = fu(kp[64]);
                uint32_t bi1 = fu(kp[68]);
                mma8(Sr[nt], ar0, ar1, ar2, ar3, br0, br1);  // qr.kr
                mma8(Sr[nt], ai0, ai1, ai2, ai3, bi0, bi1);  // + qi.ki
                mma8(Si[nt], ai0, ai1, ai2, ai3, br0, br1);  // qi.kr
                mma8(Si[nt], nr0, nr1, nr2, nr3, bi0, bi1);  // - qr.ki
            }
        }

        // magnitude + exp on FMA/ALU pipes; accumulate l; store P
        #pragma unroll
        for (int nt = 0; nt < 8; nt++) {
            float h0 = fmaf(Si[nt][0], Si[nt][0], Sr[nt][0] * Sr[nt][0]);
            float h1 = fmaf(Si[nt][1], Si[nt][1], Sr[nt][1] * Sr[nt][1]);
            float h2 = fmaf(Si[nt][2], Si[nt][2], Sr[nt][2] * Sr[nt][2]);
            float h3 = fmaf(Si[nt][3], Si[nt][3], Sr[nt][3] * Sr[nt][3]);
            float p0 = exp2p(fmaf(sqrt_nr(h0), K1, K2));
            float p1 = exp2p(fmaf(sqrt_nr(h1), K1, K2));
            float p2 = exp2p(fmaf(sqrt_nr(h2), K1, K2));
            float p3 = exp2p(fmaf(sqrt_nr(h3), K1, K2));
            l0 += p0 + p1;
            l1 += p2 + p3;
            *(float2*)(Ps + (qrow + g) * 68 + 8 * nt + 2 * tg) = make_float2(tf32f(p0), tf32f(p1));
            *(float2*)(Ps + (qrow + g + 8) * 68 + 8 * nt + 2 * tg) = make_float2(tf32f(p2), tf32f(p3));
        }
        __syncwarp();   // each warp reads only its own 16 P rows

        // O += P @ [vr|vi]
        #pragma unroll 2
        for (int ks = 0; ks < 8; ks++) {
            const int pcol = 8 * ks + tg;
            uint32_t a0 = fu(Ps[(qrow + g) * 68 + pcol]);
            uint32_t a1 = fu(Ps[(qrow + g + 8) * 68 + pcol]);
            uint32_t a2 = fu(Ps[(qrow + g) * 68 + pcol + 4]);
            uint32_t a3 = fu(Ps[(qrow + g + 8) * 68 + pcol + 4]);
            const float* v0p = Vb + (8 * ks + tg) * 136 + g;
            const float* v1p = Vb + (8 * ks + tg + 4) * 136 + g;
            #pragma unroll
            for (int nt = 0; nt < 16; nt++) {
                uint32_t b0 = fu(v0p[8 * nt]);
                uint32_t b1 = fu(v1p[8 * nt]);
                mma8(O[nt], a0, a1, a2, a3, b0, b1);
            }
        }
    }

    // epilogue: divide by row sums, write tf32-rounded merged-head layout
    l0 += __shfl_xor_sync(0xffffffffu, l0, 1);
    l0 += __shfl_xor_sync(0xffffffffu, l0, 2);
    l1 += __shfl_xor_sync(0xffffffffu, l1, 1);
    l1 += __shfl_xor_sync(0xffffffffu, l1, 2);
    const float inv0 = 1.f / l0, inv1 = 1.f / l1;

    const int b_ = bh >> 4, hh = bh & 15;
    const int q = q0 + qrow + g;
    float* dst0 = g_z + (size_t)(b_ * 2048 + q) * 2048;
    float* dst1 = g_z + (size_t)(b_ * 2048 + q + 8) * 2048;
    #pragma unroll
    for (int nt = 0; nt < 16; nt++) {
        int d0 = 8 * nt + 2 * tg;
        int col = (d0 >> 6) * 1024 + hh * 64 + (d0 & 63);
        *(float2*)(dst0 + col) = make_float2(tf32f(O[nt][0] * inv0), tf32f(O[nt][1] * inv0));
        *(float2*)(dst1 + col) = make_float2(tf32f(O[nt][2] * inv1), tf32f(O[nt][3] * inv1));
    }
}

// ---------------------------------------------------------------------------
// Final GEMM: out[m][o] = sum_k g_z[m][k]*g_wc[o][k] + g_fb[o]
// M=4096, N=1024, K=2048. cp.async double-buffered.
// ---------------------------------------------------------------------------
__global__ void __launch_bounds__(256, 2) final_mma_kernel(float* __restrict__ Outp)
{
    extern __shared__ float sm[];
    float* As = sm;
    float* Bs = sm + 2 * 128 * 36;
    const uint32_t as_u = (uint32_t)__cvta_generic_to_shared(As);
    const uint32_t bs_u = (uint32_t)__cvta_generic_to_shared(Bs);

    const int t = threadIdx.x;
    const int w = t >> 5, lane = t & 31, g = lane >> 2, tg = lane & 3;
    const int wm = w >> 2, wn = w & 3;
    const int m0 = blockIdx.y * 128;
    const int o0 = blockIdx.x * 128;

    int lr[4], lc[4];
    #pragma unroll
    for (int i = 0; i < 4; i++) { int idx = i * 256 + t; lr[i] = idx >> 3; lc[i] = (idx & 7) * 4; }

    const float* Ag = g_z + (size_t)m0 * 2048;
    const float* Bg = g_wc + (size_t)o0 * 2048;

    auto loadAB = [&](int k0, int buf) {
        const int boff = buf * 128 * 36;
        #pragma unroll
        for (int i = 0; i < 4; i++) {
            cpa16(as_u + (boff + lr[i] * 36 + lc[i]) * 4, Ag + lr[i] * 2048 + k0 + lc[i]);
            cpa16(bs_u + (boff + lr[i] * 36 + lc[i]) * 4, Bg + lr[i] * 2048 + k0 + lc[i]);
        }
        CP_COMMIT();
    };

    float acc[4][4][4];
    #pragma unroll
    for (int a = 0; a < 4; a++)
        #pragma unroll
        for (int b = 0; b < 4; b++)
            #pragma unroll
            for (int c = 0; c < 4; c++) acc[a][b][c] = 0.f;

    loadAB(0, 0);

    for (int kt = 0; kt < 64; kt++) {
        CP_WAIT0();
        __syncthreads();
        if (kt + 1 < 64) loadAB((kt + 1) * 32, (kt + 1) & 1);
        const float* Ab = As + (kt & 1) * 128 * 36;
        const float* Bb = Bs + (kt & 1) * 128 * 36;
        #pragma unroll
        for (int ks = 0; ks < 4; ks++) {
            const int col = 8 * ks + tg;
            uint32_t a[4][4];
            #pragma unroll
            for (int mt = 0; mt < 4; mt++) {
                const float* ap = Ab + (64 * wm + 16 * mt + g) * 36;
                a[mt][0] = fu(ap[col]);
                a[mt][1] = fu(ap[8 * 36 + col]);
                a[mt][2] = fu(ap[col + 4]);
                a[mt][3] = fu(ap[8 * 36 + col + 4]);
            }
            #pragma unroll
            for (int nt = 0; nt < 4; nt++) {
                const float* bp = Bb + (32 * wn + 8 * nt + g) * 36;
                uint32_t b0 = fu(bp[col]);
                uint32_t b1 = fu(bp[col + 4]);
                #pragma unroll
                for (int mt = 0; mt < 4; mt++)
                    mma8(acc[mt][nt], a[mt][0], a[mt][1], a[mt][2], a[mt][3], b0, b1);
            }
        }
    }

    const int ob = o0 + 32 * wn;
    #pragma unroll
    for (int mt = 0; mt < 4; mt++) {
        int m = m0 + 64 * wm + 16 * mt + g;
        #pragma unroll
        for (int r = 0; r < 2; r++) {
            int mm = m + 8 * r;
            float* dst = Outp + (size_t)mm * 1024;
            #pragma unroll
            for (int nt = 0; nt < 4; nt++) {
                int o = ob + 8 * nt + 2 * tg;
                float2 fb = *(const float2*)(g_fb + o);
                *(float2*)(dst + o) =
                    make_float2(acc[mt][nt][2 * r + 0] + fb.x,
                                acc[mt][nt][2 * r + 1] + fb.y);
            }
        }
    }
}

// ---------------------------------------------------------------------------
extern "C" void kernel_launch(void* const* d_in, const int* in_sizes, int n_in,
                              void* d_out, int out_size)
{
    const float* x    = (const float*)d_in[0];
    const float* qr_w = (const float*)d_in[1];
    const float* qr_b = (const float*)d_in[2];
    const float* qi_w = (const float*)d_in[3];
    const float* qi_b = (const float*)d_in[4];
    const float* kr_w = (const float*)d_in[5];
    const float* kr_b = (const float*)d_in[6];
    const float* ki_w = (const float*)d_in[7];
    const float* ki_b = (const float*)d_in[8];
    const float* vr_w = (const float*)d_in[9];
    const float* vr_b = (const float*)d_in[10];
    const float* vi_w = (const float*)d_in[11];
    const float* vi_b = (const float*)d_in[12];
    const float* or_w = (const float*)d_in[13];
    const float* or_b = (const float*)d_in[14];
    const float* oi_w = (const float*)d_in[15];
    const float* oi_b = (const float*)d_in[16];
    float* out = (float*)d_out;

    static bool attr_set = false;
    if (!attr_set) {
        cudaFuncSetAttribute(proj_mma_kernel, cudaFuncAttributeMaxDynamicSharedMemorySize, PROJ_SMEM);
        cudaFuncSetAttribute(attn_mma_kernel, cudaFuncAttributeMaxDynamicSharedMemorySize, ATT_SMEM);
        cudaFuncSetAttribute(final_mma_kernel, cudaFuncAttributeMaxDynamicSharedMemorySize, PROJ_SMEM);
        attr_set = true;
    }

    prep_kernel<<<10240, 256>>>(x, qr_w, qi_w, kr_w, ki_w, vr_w, vi_w);
    make_wc_kernel<<<2048, 256>>>(or_w, oi_w, or_b, oi_b);

    proj_mma_kernel<<<dim3(16, 32, 3), 256, PROJ_SMEM>>>(
        qr_b, qi_b, kr_b, ki_b, vr_b, vi_b);

    attn_mma_kernel<<<dim3(16, 32), 256, ATT_SMEM>>>();

    final_mma_kernel<<<dim3(8, 32), 256, PROJ_SMEM>>>(out);
}

// round 7
// speedup vs baseline: 1.4303x; 1.0366x over previous
#include <cuda_runtime.h>
#include <cstdint>

// Problem: B=2, N=2048, C=1024, H=16, D=64
// g_q/g_k/g_v: [bh=32][n=2048][128], d 0..63 real, 64..127 imag (tf32-rounded)
// g_z: [b*2048+n][2048] = [out_r(1024) | out_i(1024)] (tf32-rounded)
// g_x, g_w: tf32-rounded copies of x and the 6 QKV weights
// g_wc, g_fb: combined output weight (tf32-rounded) and bias

#define PROJ_SMEM (2 * 2 * 128 * 36 * 4)                      // 73728 B
#define ATT_SMEM  ((128 * 132 + 128 * 136 + 128 * 68) * 4)    // 172032 B

__device__ float g_q[32 * 2048 * 128];
__device__ float g_k[32 * 2048 * 128];
__device__ float g_v[32 * 2048 * 128];
__device__ float g_z[4096 * 2048];
__device__ float g_x[4096 * 1024];
__device__ float g_w[6 * 1024 * 1024];
__device__ float g_wc[1024 * 2048];
__device__ float g_fb[1024];

// ---------------------------------------------------------------------------
// helpers
// ---------------------------------------------------------------------------
__device__ __forceinline__ float tf32f(float x) {
    uint32_t r;
    asm("cvt.rna.tf32.f32 %0, %1;" : "=r"(r) : "f"(x));
    return __int_as_float(r);
}
__device__ __forceinline__ uint32_t fu(float x) { return __float_as_uint(x); }

__device__ __forceinline__ float sqrt_ap(float x) {
    float r;
    asm("sqrt.approx.f32 %0, %1;" : "=f"(r) : "f"(x));
    return r;
}
__device__ __forceinline__ float ex2_ap(float x) {
    float r;
    asm("ex2.approx.f32 %0, %1;" : "=f"(r) : "f"(x));
    return r;
}

__device__ __forceinline__ void mma8(float* d,
                                     uint32_t a0, uint32_t a1, uint32_t a2, uint32_t a3,
                                     uint32_t b0, uint32_t b1) {
    asm volatile(
        "mma.sync.aligned.m16n8k8.row.col.f32.tf32.tf32.f32 "
        "{%0,%1,%2,%3}, {%4,%5,%6,%7}, {%8,%9}, {%0,%1,%2,%3};"
        : "+f"(d[0]), "+f"(d[1]), "+f"(d[2]), "+f"(d[3])
        : "r"(a0), "r"(a1), "r"(a2), "r"(a3), "r"(b0), "r"(b1));
}

__device__ __forceinline__ void cpa16(uint32_t dst, const float* src) {
    asm volatile("cp.async.cg.shared.global [%0], [%1], 16;" :: "r"(dst), "l"(src));
}
#define CP_COMMIT() asm volatile("cp.async.commit_group;")
#define CP_WAIT0()  asm volatile("cp.async.wait_group 0;")

// ---------------------------------------------------------------------------
// Pre-round x and the 6 QKV weights into g_x / g_w (tf32).
// ---------------------------------------------------------------------------
__global__ void __launch_bounds__(256) prep_kernel(
    const float* __restrict__ x,
    const float* __restrict__ qrw, const float* __restrict__ qiw,
    const float* __restrict__ krw, const float* __restrict__ kiw,
    const float* __restrict__ vrw, const float* __restrict__ viw)
{
    int i4 = blockIdx.x * 256 + threadIdx.x;
    const float* src;
    float* dst;
    if (i4 < 1048576) {
        src = x + (size_t)i4 * 4;
        dst = g_x + (size_t)i4 * 4;
    } else {
        int j = i4 - 1048576;
        int wsel = j >> 18;
        int off = j & 262143;
        const float* wp;
        switch (wsel) {
            case 0: wp = qrw; break;
            case 1: wp = qiw; break;
            case 2: wp = krw; break;
            case 3: wp = kiw; break;
            case 4: wp = vrw; break;
            default: wp = viw; break;
        }
        src = wp + (size_t)off * 4;
        dst = g_w + (size_t)wsel * 1048576 + (size_t)off * 4;
    }
    float4 v = *(const float4*)src;
    v.x = tf32f(v.x); v.y = tf32f(v.y); v.z = tf32f(v.z); v.w = tf32f(v.w);
    *(float4*)dst = v;
}

// ---------------------------------------------------------------------------
// Combined output weight (tf32-rounded) + bias.
// ---------------------------------------------------------------------------
__global__ void __launch_bounds__(256) make_wc_kernel(
    const float* __restrict__ orw, const float* __restrict__ oiw,
    const float* __restrict__ orb, const float* __restrict__ oib)
{
    int idx = blockIdx.x * 256 + threadIdx.x;
    int o = idx >> 9;
    int k = (idx & 511) << 2;
    float4 r;
    if (k < 1024) {
        float4 a = *(const float4*)(orw + (size_t)o * 1024 + k);
        float4 b = *(const float4*)(oiw + (size_t)o * 1024 + k);
        r.x = fmaf(0.1f, b.x, a.x); r.y = fmaf(0.1f, b.y, a.y);
        r.z = fmaf(0.1f, b.z, a.z); r.w = fmaf(0.1f, b.w, a.w);
    } else {
        int kk = k - 1024;
        float4 a = *(const float4*)(orw + (size_t)o * 1024 + kk);
        float4 b = *(const float4*)(oiw + (size_t)o * 1024 + kk);
        r.x = fmaf(0.1f, a.x, -b.x); r.y = fmaf(0.1f, a.y, -b.y);
        r.z = fmaf(0.1f, a.z, -b.z); r.w = fmaf(0.1f, a.w, -b.w);
    }
    r.x = tf32f(r.x); r.y = tf32f(r.y); r.z = tf32f(r.z); r.w = tf32f(r.w);
    *(float4*)(g_wc + (size_t)o * 2048 + k) = r;
    if ((idx & 511) == 0)
        g_fb[o] = 1.1f * orb[o] - 0.9f * oib[o];
}

// ---------------------------------------------------------------------------
// Input projections: blockIdx.z = 0/1/2 -> Q/K/V.
// BM=128, BN=128, BK=32, cp.async double-buffered smem, tf32 mma.
// launch_bounds(256,2): <=128 regs -> 2 CTAs/SM.
// ---------------------------------------------------------------------------
__global__ void __launch_bounds__(256, 2) proj_mma_kernel(
    const float* __restrict__ qrb, const float* __restrict__ qib,
    const float* __restrict__ krb, const float* __restrict__ kib,
    const float* __restrict__ vrb, const float* __restrict__ vib)
{
    extern __shared__ float sm[];
    float* As = sm;                 // [2][128][36]
    float* Bs = sm + 2 * 128 * 36;  // [2][128][36]
    const uint32_t as_u = (uint32_t)__cvta_generic_to_shared(As);
    const uint32_t bs_u = (uint32_t)__cvta_generic_to_shared(Bs);

    const int t = threadIdx.x;
    const int w = t >> 5, lane = t & 31, g = lane >> 2, tg = lane & 3;
    const int wm = w >> 2, wn = w & 3;
    const int z = blockIdx.z;
    const int bx = blockIdx.x;
    const int m0 = blockIdx.y * 128;
    const bool imag = bx >= 8;
    const float* bias;
    float* Out;
    if (z == 0)      { bias = imag ? qib : qrb; Out = g_q; }
    else if (z == 1) { bias = imag ? kib : krb; Out = g_k; }
    else             { bias = imag ? vib : vrb; Out = g_v; }
    const float* W = g_w + (size_t)(z * 2 + (imag ? 1 : 0)) * 1024 * 1024;
    const int o0 = (bx & 7) * 128;

    int lr[4], lc[4];
    #pragma unroll
    for (int i = 0; i < 4; i++) { int idx = i * 256 + t; lr[i] = idx >> 3; lc[i] = (idx & 7) * 4; }

    const float* Ag = g_x + (size_t)m0 * 1024;
    const float* Bg = W + (size_t)o0 * 1024;

    auto loadAB = [&](int k0, int buf) {
        const int boff = buf * 128 * 36;
        #pragma unroll
        for (int i = 0; i < 4; i++) {
            cpa16(as_u + (boff + lr[i] * 36 + lc[i]) * 4, Ag + lr[i] * 1024 + k0 + lc[i]);
            cpa16(bs_u + (boff + lr[i] * 36 + lc[i]) * 4, Bg + lr[i] * 1024 + k0 + lc[i]);
        }
        CP_COMMIT();
    };

    float acc[4][4][4];
    #pragma unroll
    for (int a = 0; a < 4; a++)
        #pragma unroll
        for (int b = 0; b < 4; b++)
            #pragma unroll
            for (int c = 0; c < 4; c++) acc[a][b][c] = 0.f;

    loadAB(0, 0);

    for (int kt = 0; kt < 32; kt++) {
        CP_WAIT0();
        __syncthreads();
        if (kt + 1 < 32) loadAB((kt + 1) * 32, (kt + 1) & 1);
        const float* Ab = As + (kt & 1) * 128 * 36;
        const float* Bb = Bs + (kt & 1) * 128 * 36;
        #pragma unroll
        for (int ks = 0; ks < 4; ks++) {
            const int col = 8 * ks + tg;
            uint32_t a[4][4];
            #pragma unroll
            for (int mt = 0; mt < 4; mt++) {
                const float* ap = Ab + (64 * wm + 16 * mt + g) * 36;
                a[mt][0] = fu(ap[col]);
                a[mt][1] = fu(ap[8 * 36 + col]);
                a[mt][2] = fu(ap[col + 4]);
                a[mt][3] = fu(ap[8 * 36 + col + 4]);
            }
            #pragma unroll
            for (int nt = 0; nt < 4; nt++) {
                const float* bp = Bb + (32 * wn + 8 * nt + g) * 36;
                uint32_t b0 = fu(bp[col]);
                uint32_t b1 = fu(bp[col + 4]);
                #pragma unroll
                for (int mt = 0; mt < 4; mt++)
                    mma8(acc[mt][nt], a[mt][0], a[mt][1], a[mt][2], a[mt][3], b0, b1);
            }
        }
    }

    // epilogue: scatter tf32-rounded (acc + bias) into [bh][n][128]
    const int part = imag ? 1 : 0;
    const int ob = o0 + 32 * wn;
    const int hh = ob >> 6;
    #pragma unroll
    for (int mt = 0; mt < 4; mt++) {
        int m = m0 + 64 * wm + 16 * mt + g;
        #pragma unroll
        for (int r = 0; r < 2; r++) {
            int mm = m + 8 * r;
            int b_ = mm >> 11, nn = mm & 2047;
            float* dst = Out + ((size_t)(b_ * 16 + hh) * 2048 + nn) * 128 + part * 64;
            #pragma unroll
            for (int nt = 0; nt < 4; nt++) {
                int o = ob + 8 * nt + 2 * tg;
                float2 bv = *(const float2*)(bias + o);
                *(float2*)(dst + (o & 63)) =
                    make_float2(tf32f(acc[mt][nt][2 * r + 0] + bv.x),
                                tf32f(acc[mt][nt][2 * r + 1] + bv.y));
            }
        }
    }
}

// ---------------------------------------------------------------------------
// Fused complex-magnitude attention, tf32 mma + MUFU softmax.
// Block = 128 queries x one bh; 8 warps, 16 query rows each; 64-key tiles.
// Q fragments in registers; K/V cp.async double-buffered.
// Fixed-shift softmax: p = ex2(0.18034*|s| - 11.5416) == exp(0.125*|s| - 8):
// sqrt and exp2 on the MUFU pipe (parallel to tensor + fma pipes).
// ---------------------------------------------------------------------------
__global__ void __launch_bounds__(256) attn_mma_kernel()
{
    extern __shared__ float sm[];
    float* Ks0 = sm;                   // [64][132]
    float* Ks1 = sm + 64 * 132;        // [64][132]
    float* Vs0 = sm + 128 * 132;       // [64][136]
    float* Vs1 = Vs0 + 64 * 136;       // [64][136]
    float* Ps  = Vs1 + 64 * 136;       // [128][68]
    const uint32_t ks0_u = (uint32_t)__cvta_generic_to_shared(Ks0);
    const uint32_t ks1_u = (uint32_t)__cvta_generic_to_shared(Ks1);
    const uint32_t vs0_u = (uint32_t)__cvta_generic_to_shared(Vs0);
    const uint32_t vs1_u = (uint32_t)__cvta_generic_to_shared(Vs1);

    const int t = threadIdx.x;
    const int w = t >> 5, lane = t & 31, g = lane >> 2, tg = lane & 3;
    const int bh = blockIdx.y;
    const int q0 = blockIdx.x * 128;
    const int qrow = 16 * w;

    const float* Qg = g_q + ((size_t)bh * 2048 + q0) * 128;
    const float* Kg = g_k + (size_t)bh * 2048 * 128;
    const float* Vg = g_v + (size_t)bh * 2048 * 128;

    // stage Q through the K double-buffer area
    #pragma unroll
    for (int i = 0; i < 16; i++) {
        int idx = i * 256 + t;
        int row = idx >> 5, c4 = (idx & 31) * 4;
        cpa16(ks0_u + (row * 132 + c4) * 4, Qg + row * 128 + c4);
    }
    CP_COMMIT();
    CP_WAIT0();
    __syncthreads();

    // Q fragments -> registers
    float qr[8][4], qi[8][4];
    #pragma unroll
    for (int ks = 0; ks < 8; ks++) {
        const int col = 8 * ks + tg;
        const float* r0 = Ks0 + (qrow + g) * 132;
        const float* r8 = Ks0 + (qrow + g + 8) * 132;
        qr[ks][0] = r0[col];      qr[ks][1] = r8[col];
        qr[ks][2] = r0[col + 4];  qr[ks][3] = r8[col + 4];
        qi[ks][0] = r0[col + 64]; qi[ks][1] = r8[col + 64];
        qi[ks][2] = r0[col + 68]; qi[ks][3] = r8[col + 68];
    }
    __syncthreads();   // done reading staged Q before K(0) overwrites

    auto loadKV = [&](int kt, uint32_t ku, uint32_t vu) {
        const float* Kt = Kg + (size_t)kt * 64 * 128;
        const float* Vt = Vg + (size_t)kt * 64 * 128;
        #pragma unroll
        for (int i = 0; i < 8; i++) {
            int idx = i * 256 + t;
            int row = idx >> 5, c4 = (idx & 31) * 4;
            cpa16(ku + (row * 132 + c4) * 4, Kt + row * 128 + c4);
            cpa16(vu + (row * 136 + c4) * 4, Vt + row * 128 + c4);
        }
        CP_COMMIT();
    };

    float O[16][4];
    #pragma unroll
    for (int i = 0; i < 16; i++) { O[i][0] = 0.f; O[i][1] = 0.f; O[i][2] = 0.f; O[i][3] = 0.f; }
    float l0 = 0.f, l1 = 0.f;

    const float K1 = 0.18033688f;   // 0.125 * log2(e)
    const float K2 = -11.541560f;   // -8 * log2(e)

    loadKV(0, ks0_u, vs0_u);

    for (int kt = 0; kt < 32; kt++) {
        CP_WAIT0();
        __syncthreads();
        if (kt + 1 < 32)
            loadKV(kt + 1, (kt & 1) ? ks0_u : ks1_u, (kt & 1) ? vs0_u : vs1_u);
        const float* Kb = (kt & 1) ? Ks1 : Ks0;
        const float* Vb = (kt & 1) ? Vs1 : Vs0;

        float Sr[8][4], Si[8][4];
        #pragma unroll
        for (int i = 0; i < 8; i++) {
            Sr[i][0] = 0.f; Sr[i][1] = 0.f; Sr[i][2] = 0.f; Sr[i][3] = 0.f;
            Si[i][0] = 0.f; Si[i][1] = 0.f; Si[i][2] = 0.f; Si[i][3] = 0.f;
        }

        #pragma unroll 2
        for (int ks = 0; ks < 8; ks++) {
            const int col = 8 * ks + tg;
            const uint32_t ar0 = fu(qr[ks][0]), ar1 = fu(qr[ks][1]);
            const uint32_t ar2 = fu(qr[ks][2]), ar3 = fu(qr[ks][3]);
            const uint32_t ai0 = fu(qi[ks][0]), ai1 = fu(qi[ks][1]);
            const uint32_t ai2 = fu(qi[ks][2]), ai3 = fu(qi[ks][3]);
            const uint32_t nr0 = ar0 ^ 0x80000000u, nr1 = ar1 ^ 0x80000000u;
            const uint32_t nr2 = ar2 ^ 0x80000000u, nr3 = ar3 ^ 0x80000000u;
            #pragma unroll
            for (int nt = 0; nt < 8; nt++) {
                const float* kp = Kb + (8 * nt + g) * 132 + col;
                uint32_t br0 = fu(kp[0]);
                uint32_t br1 = fu(kp[4]);
                uint32_t bi0 = fu(kp[64]);
                uint32_t bi1 = fu(kp[68]);
                mma8(Sr[nt], ar0, ar1, ar2, ar3, br0, br1);  // qr.kr
                mma8(Sr[nt], ai0, ai1, ai2, ai3, bi0, bi1);  // + qi.ki
                mma8(Si[nt], ai0, ai1, ai2, ai3, br0, br1);  // qi.kr
                mma8(Si[nt], nr0, nr1, nr2, nr3, bi0, bi1);  // - qr.ki
            }
        }

        // magnitude + exp via MUFU (sqrt.approx, ex2.approx); accumulate l; store P
        #pragma unroll
        for (int nt = 0; nt < 8; nt++) {
            float h0 = fmaf(Si[nt][0], Si[nt][0], Sr[nt][0] * Sr[nt][0]);
            float h1 = fmaf(Si[nt][1], Si[nt][1], Sr[nt][1] * Sr[nt][1]);
            float h2 = fmaf(Si[nt][2], Si[nt][2], Sr[nt][2] * Sr[nt][2]);
            float h3 = fmaf(Si[nt][3], Si[nt][3], Sr[nt][3] * Sr[nt][3]);
            float p0 = ex2_ap(fmaf(sqrt_ap(h0), K1, K2));
            float p1 = ex2_ap(fmaf(sqrt_ap(h1), K1, K2));
            float p2 = ex2_ap(fmaf(sqrt_ap(h2), K1, K2));
            float p3 = ex2_ap(fmaf(sqrt_ap(h3), K1, K2));
            l0 += p0 + p1;
            l1 += p2 + p3;
            *(float2*)(Ps + (qrow + g) * 68 + 8 * nt + 2 * tg) = make_float2(tf32f(p0), tf32f(p1));
            *(float2*)(Ps + (qrow + g + 8) * 68 + 8 * nt + 2 * tg) = make_float2(tf32f(p2), tf32f(p3));
        }
        __syncwarp();   // each warp reads only its own 16 P rows

        // O += P @ [vr|vi]
        #pragma unroll 2
        for (int ks = 0; ks < 8; ks++) {
            const int pcol = 8 * ks + tg;
            uint32_t a0 = fu(Ps[(qrow + g) * 68 + pcol]);
            uint32_t a1 = fu(Ps[(qrow + g + 8) * 68 + pcol]);
            uint32_t a2 = fu(Ps[(qrow + g) * 68 + pcol + 4]);
            uint32_t a3 = fu(Ps[(qrow + g + 8) * 68 + pcol + 4]);
            const float* v0p = Vb + (8 * ks + tg) * 136 + g;
            const float* v1p = Vb + (8 * ks + tg + 4) * 136 + g;
            #pragma unroll
            for (int nt = 0; nt < 16; nt++) {
                uint32_t b0 = fu(v0p[8 * nt]);
                uint32_t b1 = fu(v1p[8 * nt]);
                mma8(O[nt], a0, a1, a2, a3, b0, b1);
            }
        }
    }

    // epilogue: divide by row sums, write tf32-rounded merged-head layout
    l0 += __shfl_xor_sync(0xffffffffu, l0, 1);
    l0 += __shfl_xor_sync(0xffffffffu, l0, 2);
    l1 += __shfl_xor_sync(0xffffffffu, l1, 1);
    l1 += __shfl_xor_sync(0xffffffffu, l1, 2);
    const float inv0 = 1.f / l0, inv1 = 1.f / l1;

    const int b_ = bh >> 4, hh = bh & 15;
    const int q = q0 + qrow + g;
    float* dst0 = g_z + (size_t)(b_ * 2048 + q) * 2048;
    float* dst1 = g_z + (size_t)(b_ * 2048 + q + 8) * 2048;
    #pragma unroll
    for (int nt = 0; nt < 16; nt++) {
        int d0 = 8 * nt + 2 * tg;
        int col = (d0 >> 6) * 1024 + hh * 64 + (d0 & 63);
        *(float2*)(dst0 + col) = make_float2(tf32f(O[nt][0] * inv0), tf32f(O[nt][1] * inv0));
        *(float2*)(dst1 + col) = make_float2(tf32f(O[nt][2] * inv1), tf32f(O[nt][3] * inv1));
    }
}

// ---------------------------------------------------------------------------
// Final GEMM: out[m][o] = sum_k g_z[m][k]*g_wc[o][k] + g_fb[o]
// M=4096, N=1024, K=2048. cp.async double-buffered.
// ---------------------------------------------------------------------------
__global__ void __launch_bounds__(256, 2) final_mma_kernel(float* __restrict__ Outp)
{
    extern __shared__ float sm[];
    float* As = sm;
    float* Bs = sm + 2 * 128 * 36;
    const uint32_t as_u = (uint32_t)__cvta_generic_to_shared(As);
    const uint32_t bs_u = (uint32_t)__cvta_generic_to_shared(Bs);

    const int t = threadIdx.x;
    const int w = t >> 5, lane = t & 31, g = lane >> 2, tg = lane & 3;
    const int wm = w >> 2, wn = w & 3;
    const int m0 = blockIdx.y * 128;
    const int o0 = blockIdx.x * 128;

    int lr[4], lc[4];
    #pragma unroll
    for (int i = 0; i < 4; i++) { int idx = i * 256 + t; lr[i] = idx >> 3; lc[i] = (idx & 7) * 4; }

    const float* Ag = g_z + (size_t)m0 * 2048;
    const float* Bg = g_wc + (size_t)o0 * 2048;

    auto loadAB = [&](int k0, int buf) {
        const int boff = buf * 128 * 36;
        #pragma unroll
        for (int i = 0; i < 4; i++) {
            cpa16(as_u + (boff + lr[i] * 36 + lc[i]) * 4, Ag + lr[i] * 2048 + k0 + lc[i]);
            cpa16(bs_u + (boff + lr[i] * 36 + lc[i]) * 4, Bg + lr[i] * 2048 + k0 + lc[i]);
        }
        CP_COMMIT();
    };

    float acc[4][4][4];
    #pragma unroll
    for (int a = 0; a < 4; a++)
        #pragma unroll
        for (int b = 0; b < 4; b++)
            #pragma unroll
            for (int c = 0; c < 4; c++) acc[a][b][c] = 0.f;

    loadAB(0, 0);

    for (int kt = 0; kt < 64; kt++) {
        CP_WAIT0();
        __syncthreads();
        if (kt + 1 < 64) loadAB((kt + 1) * 32, (kt + 1) & 1);
        const float* Ab = As + (kt & 1) * 128 * 36;
        const float* Bb = Bs + (kt & 1) * 128 * 36;
        #pragma unroll
        for (int ks = 0; ks < 4; ks++) {
            const int col = 8 * ks + tg;
            uint32_t a[4][4];
            #pragma unroll
            for (int mt = 0; mt < 4; mt++) {
                const float* ap = Ab + (64 * wm + 16 * mt + g) * 36;
                a[mt][0] = fu(ap[col]);
                a[mt][1] = fu(ap[8 * 36 + col]);
                a[mt][2] = fu(ap[col + 4]);
                a[mt][3] = fu(ap[8 * 36 + col + 4]);
            }
            #pragma unroll
            for (int nt = 0; nt < 4; nt++) {
                const float* bp = Bb + (32 * wn + 8 * nt + g) * 36;
                uint32_t b0 = fu(bp[col]);
                uint32_t b1 = fu(bp[col + 4]);
                #pragma unroll
                for (int mt = 0; mt < 4; mt++)
                    mma8(acc[mt][nt], a[mt][0], a[mt][1], a[mt][2], a[mt][3], b0, b1);
            }
        }
    }

    const int ob = o0 + 32 * wn;
    #pragma unroll
    for (int mt = 0; mt < 4; mt++) {
        int m = m0 + 64 * wm + 16 * mt + g;
        #pragma unroll
        for (int r = 0; r < 2; r++) {
            int mm = m + 8 * r;
            float* dst = Outp + (size_t)mm * 1024;
            #pragma unroll
            for (int nt = 0; nt < 4; nt++) {
                int o = ob + 8 * nt + 2 * tg;
                float2 fb = *(const float2*)(g_fb + o);
                *(float2*)(dst + o) =
                    make_float2(acc[mt][nt][2 * r + 0] + fb.x,
                                acc[mt][nt][2 * r + 1] + fb.y);
            }
        }
    }
}

// ---------------------------------------------------------------------------
extern "C" void kernel_launch(void* const* d_in, const int* in_sizes, int n_in,
                              void* d_out, int out_size)
{
    const float* x    = (const float*)d_in[0];
    const float* qr_w = (const float*)d_in[1];
    const float* qr_b = (const float*)d_in[2];
    const float* qi_w = (const float*)d_in[3];
    const float* qi_b = (const float*)d_in[4];
    const float* kr_w = (const float*)d_in[5];
    const float* kr_b = (const float*)d_in[6];
    const float* ki_w = (const float*)d_in[7];
    const float* ki_b = (const float*)d_in[8];
    const float* vr_w = (const float*)d_in[9];
    const float* vr_b = (const float*)d_in[10];
    const float* vi_w = (const float*)d_in[11];
    const float* vi_b = (const float*)d_in[12];
    const float* or_w = (const float*)d_in[13];
    const float* or_b = (const float*)d_in[14];
    const float* oi_w = (const float*)d_in[15];
    const float* oi_b = (const float*)d_in[16];
    float* out = (float*)d_out;

    static bool attr_set = false;
    if (!attr_set) {
        cudaFuncSetAttribute(proj_mma_kernel, cudaFuncAttributeMaxDynamicSharedMemorySize, PROJ_SMEM);
        cudaFuncSetAttribute(attn_mma_kernel, cudaFuncAttributeMaxDynamicSharedMemorySize, ATT_SMEM);
        cudaFuncSetAttribute(final_mma_kernel, cudaFuncAttributeMaxDynamicSharedMemorySize, PROJ_SMEM);
        attr_set = true;
    }

    prep_kernel<<<10240, 256>>>(x, qr_w, qi_w, kr_w, ki_w, vr_w, vi_w);
    make_wc_kernel<<<2048, 256>>>(or_w, oi_w, or_b, oi_b);

    proj_mma_kernel<<<dim3(16, 32, 3), 256, PROJ_SMEM>>>(
        qr_b, qi_b, kr_b, ki_b, vr_b, vi_b);

    attn_mma_kernel<<<dim3(16, 32), 256, ATT_SMEM>>>();

    final_mma_kernel<<<dim3(8, 32), 256, PROJ_SMEM>>>(out);
}

// round 8
// speedup vs baseline: 1.5724x; 1.0994x over previous
#include <cuda_runtime.h>
#include <cstdint>

// Problem: B=2, N=2048, C=1024, H=16, D=64
// g_q/g_k/g_v: [bh=32][n=2048][128], d 0..63 real, 64..127 imag (tf32-rounded)
// g_z: [b*2048+n][2048] = [out_r(1024) | out_i(1024)] (tf32-rounded)
// g_x, g_w: tf32-rounded copies of x and the 6 QKV weights
// g_wc, g_fb: combined output weight (tf32-rounded) and bias

#define PROJ_SMEM (2 * 2 * 128 * 36 * 4)                      // 73728 B
#define ATT_SMEM  ((2 * 32 * 132 + 2 * 32 * 136 + 64 * 36) * 4)  // 77824 B

__device__ float g_q[32 * 2048 * 128];
__device__ float g_k[32 * 2048 * 128];
__device__ float g_v[32 * 2048 * 128];
__device__ float g_z[4096 * 2048];
__device__ float g_x[4096 * 1024];
__device__ float g_w[6 * 1024 * 1024];
__device__ float g_wc[1024 * 2048];
__device__ float g_fb[1024];

// ---------------------------------------------------------------------------
// helpers
// ---------------------------------------------------------------------------
__device__ __forceinline__ float tf32f(float x) {
    uint32_t r;
    asm("cvt.rna.tf32.f32 %0, %1;" : "=r"(r) : "f"(x));
    return __int_as_float(r);
}
__device__ __forceinline__ uint32_t fu(float x) { return __float_as_uint(x); }

__device__ __forceinline__ float sqrt_ap(float x) {
    float r;
    asm("sqrt.approx.f32 %0, %1;" : "=f"(r) : "f"(x));
    return r;
}
__device__ __forceinline__ float ex2_ap(float x) {
    float r;
    asm("ex2.approx.f32 %0, %1;" : "=f"(r) : "f"(x));
    return r;
}

__device__ __forceinline__ void mma8(float* d,
                                     uint32_t a0, uint32_t a1, uint32_t a2, uint32_t a3,
                                     uint32_t b0, uint32_t b1) {
    asm volatile(
        "mma.sync.aligned.m16n8k8.row.col.f32.tf32.tf32.f32 "
        "{%0,%1,%2,%3}, {%4,%5,%6,%7}, {%8,%9}, {%0,%1,%2,%3};"
        : "+f"(d[0]), "+f"(d[1]), "+f"(d[2]), "+f"(d[3])
        : "r"(a0), "r"(a1), "r"(a2), "r"(a3), "r"(b0), "r"(b1));
}

__device__ __forceinline__ void cpa16(uint32_t dst, const float* src) {
    asm volatile("cp.async.cg.shared.global [%0], [%1], 16;" :: "r"(dst), "l"(src));
}
#define CP_COMMIT() asm volatile("cp.async.commit_group;")
#define CP_WAIT0()  asm volatile("cp.async.wait_group 0;")

// ---------------------------------------------------------------------------
// Pre-round x and the 6 QKV weights into g_x / g_w (tf32).
// ---------------------------------------------------------------------------
__global__ void __launch_bounds__(256) prep_kernel(
    const float* __restrict__ x,
    const float* __restrict__ qrw, const float* __restrict__ qiw,
    const float* __restrict__ krw, const float* __restrict__ kiw,
    const float* __restrict__ vrw, const float* __restrict__ viw)
{
    int i4 = blockIdx.x * 256 + threadIdx.x;
    const float* src;
    float* dst;
    if (i4 < 1048576) {
        src = x + (size_t)i4 * 4;
        dst = g_x + (size_t)i4 * 4;
    } else {
        int j = i4 - 1048576;
        int wsel = j >> 18;
        int off = j & 262143;
        const float* wp;
        switch (wsel) {
            case 0: wp = qrw; break;
            case 1: wp = qiw; break;
            case 2: wp = krw; break;
            case 3: wp = kiw; break;
            case 4: wp = vrw; break;
            default: wp = viw; break;
        }
        src = wp + (size_t)off * 4;
        dst = g_w + (size_t)wsel * 1048576 + (size_t)off * 4;
    }
    float4 v = *(const float4*)src;
    v.x = tf32f(v.x); v.y = tf32f(v.y); v.z = tf32f(v.z); v.w = tf32f(v.w);
    *(float4*)dst = v;
}

// ---------------------------------------------------------------------------
// Combined output weight (tf32-rounded) + bias.
// ---------------------------------------------------------------------------
__global__ void __launch_bounds__(256) make_wc_kernel(
    const float* __restrict__ orw, const float* __restrict__ oiw,
    const float* __restrict__ orb, const float* __restrict__ oib)
{
    int idx = blockIdx.x * 256 + threadIdx.x;
    int o = idx >> 9;
    int k = (idx & 511) << 2;
    float4 r;
    if (k < 1024) {
        float4 a = *(const float4*)(orw + (size_t)o * 1024 + k);
        float4 b = *(const float4*)(oiw + (size_t)o * 1024 + k);
        r.x = fmaf(0.1f, b.x, a.x); r.y = fmaf(0.1f, b.y, a.y);
        r.z = fmaf(0.1f, b.z, a.z); r.w = fmaf(0.1f, b.w, a.w);
    } else {
        int kk = k - 1024;
        float4 a = *(const float4*)(orw + (size_t)o * 1024 + kk);
        float4 b = *(const float4*)(oiw + (size_t)o * 1024 + kk);
        r.x = fmaf(0.1f, a.x, -b.x); r.y = fmaf(0.1f, a.y, -b.y);
        r.z = fmaf(0.1f, a.z, -b.z); r.w = fmaf(0.1f, a.w, -b.w);
    }
    r.x = tf32f(r.x); r.y = tf32f(r.y); r.z = tf32f(r.z); r.w = tf32f(r.w);
    *(float4*)(g_wc + (size_t)o * 2048 + k) = r;
    if ((idx & 511) == 0)
        g_fb[o] = 1.1f * orb[o] - 0.9f * oib[o];
}

// ---------------------------------------------------------------------------
// Input projections: blockIdx.z = 0/1/2 -> Q/K/V.
// BM=128, BN=128, BK=32, cp.async double-buffered smem, tf32 mma.
// launch_bounds(256,2): <=128 regs -> 2 CTAs/SM.
// ---------------------------------------------------------------------------
__global__ void __launch_bounds__(256, 2) proj_mma_kernel(
    const float* __restrict__ qrb, const float* __restrict__ qib,
    const float* __restrict__ krb, const float* __restrict__ kib,
    const float* __restrict__ vrb, const float* __restrict__ vib)
{
    extern __shared__ float sm[];
    float* As = sm;                 // [2][128][36]
    float* Bs = sm + 2 * 128 * 36;  // [2][128][36]
    const uint32_t as_u = (uint32_t)__cvta_generic_to_shared(As);
    const uint32_t bs_u = (uint32_t)__cvta_generic_to_shared(Bs);

    const int t = threadIdx.x;
    const int w = t >> 5, lane = t & 31, g = lane >> 2, tg = lane & 3;
    const int wm = w >> 2, wn = w & 3;
    const int z = blockIdx.z;
    const int bx = blockIdx.x;
    const int m0 = blockIdx.y * 128;
    const bool imag = bx >= 8;
    const float* bias;
    float* Out;
    if (z == 0)      { bias = imag ? qib : qrb; Out = g_q; }
    else if (z == 1) { bias = imag ? kib : krb; Out = g_k; }
    else             { bias = imag ? vib : vrb; Out = g_v; }
    const float* W = g_w + (size_t)(z * 2 + (imag ? 1 : 0)) * 1024 * 1024;
    const int o0 = (bx & 7) * 128;

    int lr[4], lc[4];
    #pragma unroll
    for (int i = 0; i < 4; i++) { int idx = i * 256 + t; lr[i] = idx >> 3; lc[i] = (idx & 7) * 4; }

    const float* Ag = g_x + (size_t)m0 * 1024;
    const float* Bg = W + (size_t)o0 * 1024;

    auto loadAB = [&](int k0, int buf) {
        const int boff = buf * 128 * 36;
        #pragma unroll
        for (int i = 0; i < 4; i++) {
            cpa16(as_u + (boff + lr[i] * 36 + lc[i]) * 4, Ag + lr[i] * 1024 + k0 + lc[i]);
            cpa16(bs_u + (boff + lr[i] * 36 + lc[i]) * 4, Bg + lr[i] * 1024 + k0 + lc[i]);
        }
        CP_COMMIT();
    };

    float acc[4][4][4];
    #pragma unroll
    for (int a = 0; a < 4; a++)
        #pragma unroll
        for (int b = 0; b < 4; b++)
            #pragma unroll
            for (int c = 0; c < 4; c++) acc[a][b][c] = 0.f;

    loadAB(0, 0);

    for (int kt = 0; kt < 32; kt++) {
        CP_WAIT0();
        __syncthreads();
        if (kt + 1 < 32) loadAB((kt + 1) * 32, (kt + 1) & 1);
        const float* Ab = As + (kt & 1) * 128 * 36;
        const float* Bb = Bs + (kt & 1) * 128 * 36;
        #pragma unroll
        for (int ks = 0; ks < 4; ks++) {
            const int col = 8 * ks + tg;
            uint32_t a[4][4];
            #pragma unroll
            for (int mt = 0; mt < 4; mt++) {
                const float* ap = Ab + (64 * wm + 16 * mt + g) * 36;
                a[mt][0] = fu(ap[col]);
                a[mt][1] = fu(ap[8 * 36 + col]);
                a[mt][2] = fu(ap[col + 4]);
                a[mt][3] = fu(ap[8 * 36 + col + 4]);
            }
            #pragma unroll
            for (int nt = 0; nt < 4; nt++) {
                const float* bp = Bb + (32 * wn + 8 * nt + g) * 36;
                uint32_t b0 = fu(bp[col]);
                uint32_t b1 = fu(bp[col + 4]);
                #pragma unroll
                for (int mt = 0; mt < 4; mt++)
                    mma8(acc[mt][nt], a[mt][0], a[mt][1], a[mt][2], a[mt][3], b0, b1);
            }
        }
    }

    // epilogue: scatter tf32-rounded (acc + bias) into [bh][n][128]
    const int part = imag ? 1 : 0;
    const int ob = o0 + 32 * wn;
    const int hh = ob >> 6;
    #pragma unroll
    for (int mt = 0; mt < 4; mt++) {
        int m = m0 + 64 * wm + 16 * mt + g;
        #pragma unroll
        for (int r = 0; r < 2; r++) {
            int mm = m + 8 * r;
            int b_ = mm >> 11, nn = mm & 2047;
            float* dst = Out + ((size_t)(b_ * 16 + hh) * 2048 + nn) * 128 + part * 64;
            #pragma unroll
            for (int nt = 0; nt < 4; nt++) {
                int o = ob + 8 * nt + 2 * tg;
                float2 bv = *(const float2*)(bias + o);
                *(float2*)(dst + (o & 63)) =
                    make_float2(tf32f(acc[mt][nt][2 * r + 0] + bv.x),
                                tf32f(acc[mt][nt][2 * r + 1] + bv.y));
            }
        }
    }
}

// ---------------------------------------------------------------------------
// Fused complex-magnitude attention, tf32 mma + MUFU softmax.
// Block = 64 queries x one bh; 4 warps (128 threads), 16 query rows/warp;
// 32-key tiles, 64 tiles. smem 77.8KB -> 2 independent CTAs per SM.
// Q fragments in registers; K/V cp.async double-buffered.
// Fixed-shift softmax: p = ex2(0.18034*|s| - 11.5416) == exp(0.125*|s| - 8).
// ---------------------------------------------------------------------------
__global__ void __launch_bounds__(128, 2) attn_mma_kernel()
{
    extern __shared__ float sm[];
    float* Ks0 = sm;                   // [32][132]
    float* Ks1 = sm + 32 * 132;        // [32][132]
    float* Vs0 = sm + 2 * 32 * 132;    // [32][136]
    float* Vs1 = Vs0 + 32 * 136;       // [32][136]
    float* Ps  = Vs1 + 32 * 136;       // [64][36]
    const uint32_t ks0_u = (uint32_t)__cvta_generic_to_shared(Ks0);
    const uint32_t ks1_u = (uint32_t)__cvta_generic_to_shared(Ks1);
    const uint32_t vs0_u = (uint32_t)__cvta_generic_to_shared(Vs0);
    const uint32_t vs1_u = (uint32_t)__cvta_generic_to_shared(Vs1);

    const int t = threadIdx.x;
    const int w = t >> 5, lane = t & 31, g = lane >> 2, tg = lane & 3;
    const int bh = blockIdx.y;
    const int q0 = blockIdx.x * 64;
    const int qrow = 16 * w;

    const float* Qg = g_q + ((size_t)bh * 2048 + q0) * 128;
    const float* Kg = g_k + (size_t)bh * 2048 * 128;
    const float* Vg = g_v + (size_t)bh * 2048 * 128;

    // stage Q (64 rows x 128, stride 132) through the K double-buffer area
    #pragma unroll
    for (int i = 0; i < 16; i++) {
        int idx = i * 128 + t;
        int row = idx >> 5, c4 = (idx & 31) * 4;
        cpa16(ks0_u + (row * 132 + c4) * 4, Qg + row * 128 + c4);
    }
    CP_COMMIT();
    CP_WAIT0();
    __syncthreads();

    // Q fragments -> registers
    float qr[8][4], qi[8][4];
    #pragma unroll
    for (int ks = 0; ks < 8; ks++) {
        const int col = 8 * ks + tg;
        const float* r0 = sm + (qrow + g) * 132;
        const float* r8 = sm + (qrow + g + 8) * 132;
        qr[ks][0] = r0[col];      qr[ks][1] = r8[col];
        qr[ks][2] = r0[col + 4];  qr[ks][3] = r8[col + 4];
        qi[ks][0] = r0[col + 64]; qi[ks][1] = r8[col + 64];
        qi[ks][2] = r0[col + 68]; qi[ks][3] = r8[col + 68];
    }
    __syncthreads();   // done reading staged Q before K(0) overwrites

    auto loadKV = [&](int kt, uint32_t ku, uint32_t vu) {
        const float* Kt = Kg + (size_t)kt * 32 * 128;
        const float* Vt = Vg + (size_t)kt * 32 * 128;
        #pragma unroll
        for (int i = 0; i < 8; i++) {
            int idx = i * 128 + t;
            int row = idx >> 5, c4 = (idx & 31) * 4;
            cpa16(ku + (row * 132 + c4) * 4, Kt + row * 128 + c4);
            cpa16(vu + (row * 136 + c4) * 4, Vt + row * 128 + c4);
        }
        CP_COMMIT();
    };

    float O[16][4];
    #pragma unroll
    for (int i = 0; i < 16; i++) { O[i][0] = 0.f; O[i][1] = 0.f; O[i][2] = 0.f; O[i][3] = 0.f; }
    float l0 = 0.f, l1 = 0.f;

    const float K1 = 0.18033688f;   // 0.125 * log2(e)
    const float K2 = -11.541560f;   // -8 * log2(e)

    loadKV(0, ks0_u, vs0_u);

    for (int kt = 0; kt < 64; kt++) {
        CP_WAIT0();
        __syncthreads();
        if (kt + 1 < 64)
            loadKV(kt + 1, (kt & 1) ? ks0_u : ks1_u, (kt & 1) ? vs0_u : vs1_u);
        const float* Kb = (kt & 1) ? Ks1 : Ks0;
        const float* Vb = (kt & 1) ? Vs1 : Vs0;

        float Sr[4][4], Si[4][4];
        #pragma unroll
        for (int i = 0; i < 4; i++) {
            Sr[i][0] = 0.f; Sr[i][1] = 0.f; Sr[i][2] = 0.f; Sr[i][3] = 0.f;
            Si[i][0] = 0.f; Si[i][1] = 0.f; Si[i][2] = 0.f; Si[i][3] = 0.f;
        }

        #pragma unroll 2
        for (int ks = 0; ks < 8; ks++) {
            const int col = 8 * ks + tg;
            const uint32_t ar0 = fu(qr[ks][0]), ar1 = fu(qr[ks][1]);
            const uint32_t ar2 = fu(qr[ks][2]), ar3 = fu(qr[ks][3]);
            const uint32_t ai0 = fu(qi[ks][0]), ai1 = fu(qi[ks][1]);
            const uint32_t ai2 = fu(qi[ks][2]), ai3 = fu(qi[ks][3]);
            const uint32_t nr0 = ar0 ^ 0x80000000u, nr1 = ar1 ^ 0x80000000u;
            const uint32_t nr2 = ar2 ^ 0x80000000u, nr3 = ar3 ^ 0x80000000u;
            #pragma unroll
            for (int nt = 0; nt < 4; nt++) {
                const float* kp = Kb + (8 * nt + g) * 132 + col;
                uint32_t br0 = fu(kp[0]);
                uint32_t br1 = fu(kp[4]);
                uint32_t bi0 = fu(kp[64]);
                uint32_t bi1 = fu(kp[68]);
                mma8(Sr[nt], ar0, ar1, ar2, ar3, br0, br1);  // qr.kr
                mma8(Sr[nt], ai0, ai1, ai2, ai3, bi0, bi1);  // + qi.ki
                mma8(Si[nt], ai0, ai1, ai2, ai3, br0, br1);  // qi.kr
                mma8(Si[nt], nr0, nr1, nr2, nr3, bi0, bi1);  // - qr.ki
            }
        }

        // magnitude + exp via MUFU; accumulate l; store P
        #pragma unroll
        for (int nt = 0; nt < 4; nt++) {
            float h0 = fmaf(Si[nt][0], Si[nt][0], Sr[nt][0] * Sr[nt][0]);
            float h1 = fmaf(Si[nt][1], Si[nt][1], Sr[nt][1] * Sr[nt][1]);
            float h2 = fmaf(Si[nt][2], Si[nt][2], Sr[nt][2] * Sr[nt][2]);
            float h3 = fmaf(Si[nt][3], Si[nt][3], Sr[nt][3] * Sr[nt][3]);
            float p0 = ex2_ap(fmaf(sqrt_ap(h0), K1, K2));
            float p1 = ex2_ap(fmaf(sqrt_ap(h1), K1, K2));
            float p2 = ex2_ap(fmaf(sqrt_ap(h2), K1, K2));
            float p3 = ex2_ap(fmaf(sqrt_ap(h3), K1, K2));
            l0 += p0 + p1;
            l1 += p2 + p3;
            *(float2*)(Ps + (qrow + g) * 36 + 8 * nt + 2 * tg) = make_float2(tf32f(p0), tf32f(p1));
            *(float2*)(Ps + (qrow + g + 8) * 36 + 8 * nt + 2 * tg) = make_float2(tf32f(p2), tf32f(p3));
        }
        __syncwarp();   // each warp reads only its own 16 P rows

        // O += P @ [vr|vi]
        #pragma unroll
        for (int ks = 0; ks < 4; ks++) {
            const int pcol = 8 * ks + tg;
            uint32_t a0 = fu(Ps[(qrow + g) * 36 + pcol]);
            uint32_t a1 = fu(Ps[(qrow + g + 8) * 36 + pcol]);
            uint32_t a2 = fu(Ps[(qrow + g) * 36 + pcol + 4]);
            uint32_t a3 = fu(Ps[(qrow + g + 8) * 36 + pcol + 4]);
            const float* v0p = Vb + (8 * ks + tg) * 136 + g;
            const float* v1p = Vb + (8 * ks + tg + 4) * 136 + g;
            #pragma unroll
            for (int nt = 0; nt < 16; nt++) {
                uint32_t b0 = fu(v0p[8 * nt]);
                uint32_t b1 = fu(v1p[8 * nt]);
                mma8(O[nt], a0, a1, a2, a3, b0, b1);
            }
        }
    }

    // epilogue: divide by row sums, write tf32-rounded merged-head layout
    l0 += __shfl_xor_sync(0xffffffffu, l0, 1);
    l0 += __shfl_xor_sync(0xffffffffu, l0, 2);
    l1 += __shfl_xor_sync(0xffffffffu, l1, 1);
    l1 += __shfl_xor_sync(0xffffffffu, l1, 2);
    const float inv0 = 1.f / l0, inv1 = 1.f / l1;

    const int b_ = bh >> 4, hh = bh & 15;
    const int q = q0 + qrow + g;
    float* dst0 = g_z + (size_t)(b_ * 2048 + q) * 2048;
    float* dst1 = g_z + (size_t)(b_ * 2048 + q + 8) * 2048;
    #pragma unroll
    for (int nt = 0; nt < 16; nt++) {
        int d0 = 8 * nt + 2 * tg;
        int col = (d0 >> 6) * 1024 + hh * 64 + (d0 & 63);
        *(float2*)(dst0 + col) = make_float2(tf32f(O[nt][0] * inv0), tf32f(O[nt][1] * inv0));
        *(float2*)(dst1 + col) = make_float2(tf32f(O[nt][2] * inv1), tf32f(O[nt][3] * inv1));
    }
}

// ---------------------------------------------------------------------------
// Final GEMM: out[m][o] = sum_k g_z[m][k]*g_wc[o][k] + g_fb[o]
// M=4096, N=1024, K=2048. cp.async double-buffered.
// ---------------------------------------------------------------------------
__global__ void __launch_bounds__(256, 2) final_mma_kernel(float* __restrict__ Outp)
{
    extern __shared__ float sm[];
    float* As = sm;
    float* Bs = sm + 2 * 128 * 36;
    const uint32_t as_u = (uint32_t)__cvta_generic_to_shared(As);
    const uint32_t bs_u = (uint32_t)__cvta_generic_to_shared(Bs);

    const int t = threadIdx.x;
    const int w = t >> 5, lane = t & 31, g = lane >> 2, tg = lane & 3;
    const int wm = w >> 2, wn = w & 3;
    const int m0 = blockIdx.y * 128;
    const int o0 = blockIdx.x * 128;

    int lr[4], lc[4];
    #pragma unroll
    for (int i = 0; i < 4; i++) { int idx = i * 256 + t; lr[i] = idx >> 3; lc[i] = (idx & 7) * 4; }

    const float* Ag = g_z + (size_t)m0 * 2048;
    const float* Bg = g_wc + (size_t)o0 * 2048;

    auto loadAB = [&](int k0, int buf) {
        const int boff = buf * 128 * 36;
        #pragma unroll
        for (int i = 0; i < 4; i++) {
            cpa16(as_u + (boff + lr[i] * 36 + lc[i]) * 4, Ag + lr[i] * 2048 + k0 + lc[i]);
            cpa16(bs_u + (boff + lr[i] * 36 + lc[i]) * 4, Bg + lr[i] * 2048 + k0 + lc[i]);
        }
        CP_COMMIT();
    };

    float acc[4][4][4];
    #pragma unroll
    for (int a = 0; a < 4; a++)
        #pragma unroll
        for (int b = 0; b < 4; b++)
            #pragma unroll
            for (int c = 0; c < 4; c++) acc[a][b][c] = 0.f;

    loadAB(0, 0);

    for (int kt = 0; kt < 64; kt++) {
        CP_WAIT0();
        __syncthreads();
        if (kt + 1 < 64) loadAB((kt + 1) * 32, (kt + 1) & 1);
        const float* Ab = As + (kt & 1) * 128 * 36;
        const float* Bb = Bs + (kt & 1) * 128 * 36;
        #pragma unroll
        for (int ks = 0; ks < 4; ks++) {
            const int col = 8 * ks + tg;
            uint32_t a[4][4];
            #pragma unroll
            for (int mt = 0; mt < 4; mt++) {
                const float* ap = Ab + (64 * wm + 16 * mt + g) * 36;
                a[mt][0] = fu(ap[col]);
                a[mt][1] = fu(ap[8 * 36 + col]);
                a[mt][2] = fu(ap[col + 4]);
                a[mt][3] = fu(ap[8 * 36 + col + 4]);
            }
            #pragma unroll
            for (int nt = 0; nt < 4; nt++) {
                const float* bp = Bb + (32 * wn + 8 * nt + g) * 36;
                uint32_t b0 = fu(bp[col]);
                uint32_t b1 = fu(bp[col + 4]);
                #pragma unroll
                for (int mt = 0; mt < 4; mt++)
                    mma8(acc[mt][nt], a[mt][0], a[mt][1], a[mt][2], a[mt][3], b0, b1);
            }
        }
    }

    const int ob = o0 + 32 * wn;
    #pragma unroll
    for (int mt = 0; mt < 4; mt++) {
        int m = m0 + 64 * wm + 16 * mt + g;
        #pragma unroll
        for (int r = 0; r < 2; r++) {
            int mm = m + 8 * r;
            float* dst = Outp + (size_t)mm * 1024;
            #pragma unroll
            for (int nt = 0; nt < 4; nt++) {
                int o = ob + 8 * nt + 2 * tg;
                float2 fb = *(const float2*)(g_fb + o);
                *(float2*)(dst + o) =
                    make_float2(acc[mt][nt][2 * r + 0] + fb.x,
                                acc[mt][nt][2 * r + 1] + fb.y);
            }
        }
    }
}

// ---------------------------------------------------------------------------
extern "C" void kernel_launch(void* const* d_in, const int* in_sizes, int n_in,
                              void* d_out, int out_size)
{
    const float* x    = (const float*)d_in[0];
    const float* qr_w = (const float*)d_in[1];
    const float* qr_b = (const float*)d_in[2];
    const float* qi_w = (const float*)d_in[3];
    const float* qi_b = (const float*)d_in[4];
    const float* kr_w = (const float*)d_in[5];
    const float* kr_b = (const float*)d_in[6];
    const float* ki_w = (const float*)d_in[7];
    const float* ki_b = (const float*)d_in[8];
    const float* vr_w = (const float*)d_in[9];
    const float* vr_b = (const float*)d_in[10];
    const float* vi_w = (const float*)d_in[11];
    const float* vi_b = (const float*)d_in[12];
    const float* or_w = (const float*)d_in[13];
    const float* or_b = (const float*)d_in[14];
    const float* oi_w = (const float*)d_in[15];
    const float* oi_b = (const float*)d_in[16];
    float* out = (float*)d_out;

    static bool attr_set = false;
    if (!attr_set) {
        cudaFuncSetAttribute(proj_mma_kernel, cudaFuncAttributeMaxDynamicSharedMemorySize, PROJ_SMEM);
        cudaFuncSetAttribute(attn_mma_kernel, cudaFuncAttributeMaxDynamicSharedMemorySize, ATT_SMEM);
        cudaFuncSetAttribute(final_mma_kernel, cudaFuncAttributeMaxDynamicSharedMemorySize, PROJ_SMEM);
        attr_set = true;
    }

    prep_kernel<<<10240, 256>>>(x, qr_w, qi_w, kr_w, ki_w, vr_w, vi_w);
    make_wc_kernel<<<2048, 256>>>(or_w, oi_w, or_b, oi_b);

    proj_mma_kernel<<<dim3(16, 32, 3), 256, PROJ_SMEM>>>(
        qr_b, qi_b, kr_b, ki_b, vr_b, vi_b);

    attn_mma_kernel<<<dim3(32, 32), 128, ATT_SMEM>>>();

    final_mma_kernel<<<dim3(8, 32), 256, PROJ_SMEM>>>(out);
}